// round 4
// baseline (speedup 1.0000x reference)
#include <cuda_runtime.h>
#include <math.h>

#define NN      10000
#define NG      64
#define ET      330000   // E0 + self loops

// ---------------- device scratch (static; no allocation) ----------------
__device__ float g_xl1[NN * 1024];   // x @ W1          [N, 8*128]
__device__ float g_h1 [NN * 1024];   // layer1 output   [N, 1024]
__device__ float g_as1[NN * 8];
__device__ float g_ad1[NN * 8];
__device__ float g_xl2[NN * 128];    // h1 @ W2         [N, 128]
__device__ float g_as2[NN];
__device__ float g_ad2[NN];
__device__ float g_h2 [NN * 128];    // layer2 output
__device__ float g_pooled[NG * 128];
__device__ int   g_cnt[NN];
__device__ int   g_cur[NN];
__device__ int   g_off[NN + 1];
__device__ int   g_csr_src[ET];

// ---------------- helpers ----------------
__device__ __forceinline__ void get_edge(const int* ei, int E0, int e,
                                         int& s, int& d) {
    if (e < E0) { s = ei[e]; d = ei[E0 + e]; }
    else        { s = e - E0; d = e - E0; }
}

__device__ __forceinline__ float lrelu(float x) { return x > 0.f ? x : 0.2f * x; }
__device__ __forceinline__ float elu(float x)   { return x > 0.f ? x : expm1f(x); }

__device__ __forceinline__ float tf32r(float x) {
    unsigned u;
    asm("cvt.rna.tf32.f32 %0, %1;" : "=r"(u) : "f"(x));
    return __uint_as_float(u);
}

__device__ __forceinline__ void mma_tf32(float* d, const unsigned* a, const unsigned* b) {
    asm volatile(
        "mma.sync.aligned.m16n8k8.row.col.f32.tf32.tf32.f32 "
        "{%0,%1,%2,%3},{%4,%5,%6,%7},{%8,%9},{%0,%1,%2,%3};"
        : "+f"(d[0]), "+f"(d[1]), "+f"(d[2]), "+f"(d[3])
        : "r"(a[0]), "r"(a[1]), "r"(a[2]), "r"(a[3]), "r"(b[0]), "r"(b[1]));
}

// ---------------- CSR build ----------------
__global__ void k_init_counts() {
    int i = blockIdx.x * blockDim.x + threadIdx.x;
    if (i < NN) { g_cnt[i] = 0; g_cur[i] = 0; }
}

__global__ void k_count(const int* ei, int E0) {
    int e = blockIdx.x * blockDim.x + threadIdx.x;
    if (e >= E0 + NN) return;
    int s, d; get_edge(ei, E0, e, s, d);
    if ((unsigned)s >= NN || (unsigned)d >= NN) return;
    atomicAdd(&g_cnt[d], 1);
}

__global__ void k_scan() {
    __shared__ int part[1024];
    const int CH = 10;
    int tid = threadIdx.x;
    int local[CH];
    int s = 0;
    #pragma unroll
    for (int i = 0; i < CH; i++) {
        int idx = tid * CH + i;
        int v = (idx < NN) ? g_cnt[idx] : 0;
        local[i] = s; s += v;
    }
    part[tid] = s;
    __syncthreads();
    for (int o = 1; o < 1024; o <<= 1) {
        int v = (tid >= o) ? part[tid - o] : 0;
        __syncthreads();
        part[tid] += v;
        __syncthreads();
    }
    int pre = tid ? part[tid - 1] : 0;
    #pragma unroll
    for (int i = 0; i < CH; i++) {
        int idx = tid * CH + i;
        if (idx < NN) g_off[idx] = pre + local[i];
    }
    if (tid == 1023) g_off[NN] = part[1023];
}

__global__ void k_scatter(const int* ei, int E0) {
    int e = blockIdx.x * blockDim.x + threadIdx.x;
    if (e >= E0 + NN) return;
    int s, d; get_edge(ei, E0, e, s, d);
    if ((unsigned)s >= NN || (unsigned)d >= NN) return;
    int pos = atomicAdd(&g_cur[d], 1);
    g_csr_src[g_off[d] + pos] = s;
}

// ---------------- TF32x3 tensor-core GEMM: C[M,N] = A[M,K] @ B[K,N] ------------
// Block tile 128x64, BK=16, 256 threads (8 warps: 4m x 2n, warp tile 32x32).
// A split hi/lo staged as smem [k][m] (pad 132); B as [k][n] (pad 68).
// a_sel: 0 -> external A, 1 -> g_h1.  c_sel: 0 -> g_xl1, 1 -> g_xl2.
__global__ void k_mma(const float* __restrict__ Aext, const float* __restrict__ B,
                      int M, int N, int K, int a_sel, int c_sel) {
    const float* A = a_sel ? g_h1 : Aext;
    float* C = c_sel ? g_xl2 : g_xl1;

    __shared__ float Ah[16][132];
    __shared__ float Al[16][132];
    __shared__ float Bh[16][68];
    __shared__ float Bl[16][68];

    const int tid  = threadIdx.x;
    const int lane = tid & 31;
    const int wid  = tid >> 5;
    const int tq   = lane >> 2;     // 0..7
    const int t4   = lane & 3;      // 0..3
    const int warp_m = (wid >> 1) * 32;   // 0,32,64,96
    const int warp_n = (wid & 1) * 32;    // 0,32

    const int brow = blockIdx.y * 128;
    const int bcol = blockIdx.x * 64;

    // A loader mapping: row = tid>>1 (0..127), kq = (tid&1)*8 -> float4 x2 over k
    const int a_row = tid >> 1;
    const int a_kq  = (tid & 1) * 8;
    // B loader mapping: krow = tid>>4 (0..15), col = (tid&15)*4
    const int b_k   = tid >> 4;
    const int b_c   = (tid & 15) * 4;

    float acc[2][4][4];
    #pragma unroll
    for (int i = 0; i < 2; i++)
        #pragma unroll
        for (int j = 0; j < 4; j++)
            #pragma unroll
            for (int r = 0; r < 4; r++) acc[i][j][r] = 0.f;

    for (int k0 = 0; k0 < K; k0 += 16) {
        // --- stage A (128 x 16), split hi/lo, store transposed [k][m] ---
        {
            int grow = brow + a_row;
            #pragma unroll
            for (int half = 0; half < 2; half++) {
                int kk = a_kq + half * 4;
                float4 v = make_float4(0.f, 0.f, 0.f, 0.f);
                if (grow < M) v = *(const float4*)(A + (size_t)grow * K + k0 + kk);
                float h, l;
                h = tf32r(v.x); l = tf32r(v.x - h); Ah[kk + 0][a_row] = h; Al[kk + 0][a_row] = l;
                h = tf32r(v.y); l = tf32r(v.y - h); Ah[kk + 1][a_row] = h; Al[kk + 1][a_row] = l;
                h = tf32r(v.z); l = tf32r(v.z - h); Ah[kk + 2][a_row] = h; Al[kk + 2][a_row] = l;
                h = tf32r(v.w); l = tf32r(v.w - h); Ah[kk + 3][a_row] = h; Al[kk + 3][a_row] = l;
            }
        }
        // --- stage B (16 x 64), split hi/lo ---
        {
            float4 v = *(const float4*)(B + (size_t)(k0 + b_k) * N + bcol + b_c);
            float h, l;
            h = tf32r(v.x); l = tf32r(v.x - h); Bh[b_k][b_c + 0] = h; Bl[b_k][b_c + 0] = l;
            h = tf32r(v.y); l = tf32r(v.y - h); Bh[b_k][b_c + 1] = h; Bl[b_k][b_c + 1] = l;
            h = tf32r(v.z); l = tf32r(v.z - h); Bh[b_k][b_c + 2] = h; Bl[b_k][b_c + 2] = l;
            h = tf32r(v.w); l = tf32r(v.w - h); Bh[b_k][b_c + 3] = h; Bl[b_k][b_c + 3] = l;
        }
        __syncthreads();

        #pragma unroll
        for (int ks = 0; ks < 16; ks += 8) {
            // load A fragments (2 m-frags), hi+lo
            unsigned ah[2][4], al[2][4];
            #pragma unroll
            for (int fm = 0; fm < 2; fm++) {
                int r = warp_m + fm * 16 + tq;
                ah[fm][0] = __float_as_uint(Ah[ks + t4    ][r    ]);
                ah[fm][1] = __float_as_uint(Ah[ks + t4    ][r + 8]);
                ah[fm][2] = __float_as_uint(Ah[ks + t4 + 4][r    ]);
                ah[fm][3] = __float_as_uint(Ah[ks + t4 + 4][r + 8]);
                al[fm][0] = __float_as_uint(Al[ks + t4    ][r    ]);
                al[fm][1] = __float_as_uint(Al[ks + t4    ][r + 8]);
                al[fm][2] = __float_as_uint(Al[ks + t4 + 4][r    ]);
                al[fm][3] = __float_as_uint(Al[ks + t4 + 4][r + 8]);
            }
            // load B fragments (4 n-frags), hi+lo
            unsigned bh[4][2], bl[4][2];
            #pragma unroll
            for (int fn = 0; fn < 4; fn++) {
                int c = warp_n + fn * 8 + tq;
                bh[fn][0] = __float_as_uint(Bh[ks + t4    ][c]);
                bh[fn][1] = __float_as_uint(Bh[ks + t4 + 4][c]);
                bl[fn][0] = __float_as_uint(Bl[ks + t4    ][c]);
                bl[fn][1] = __float_as_uint(Bl[ks + t4 + 4][c]);
            }
            #pragma unroll
            for (int fm = 0; fm < 2; fm++)
                #pragma unroll
                for (int fn = 0; fn < 4; fn++) {
                    mma_tf32(acc[fm][fn], ah[fm], bl[fn]);   // Ah*Bl
                    mma_tf32(acc[fm][fn], al[fm], bh[fn]);   // Al*Bh
                    mma_tf32(acc[fm][fn], ah[fm], bh[fn]);   // Ah*Bh
                }
        }
        __syncthreads();
    }

    // epilogue: c0,c1 -> (row tq, cols 2t4,2t4+1), c2,c3 -> row tq+8
    #pragma unroll
    for (int fm = 0; fm < 2; fm++) {
        int r0 = brow + warp_m + fm * 16 + tq;
        int r1 = r0 + 8;
        #pragma unroll
        for (int fn = 0; fn < 4; fn++) {
            int c = bcol + warp_n + fn * 8 + 2 * t4;
            if (r0 < M) *(float2*)(C + (size_t)r0 * N + c) = make_float2(acc[fm][fn][0], acc[fm][fn][1]);
            if (r1 < M) *(float2*)(C + (size_t)r1 * N + c) = make_float2(acc[fm][fn][2], acc[fm][fn][3]);
        }
    }
}

// ---------------- alpha dot products ----------------
__global__ void k_alpha1(const float* __restrict__ a_src,
                         const float* __restrict__ a_dst) {
    int n = blockIdx.x;
    int h = threadIdx.x >> 5;
    int lane = threadIdx.x & 31;
    const float4 v  = *(const float4*)(g_xl1 + (size_t)n * 1024 + h * 128 + lane * 4);
    const float4 as = *(const float4*)(a_src + h * 128 + lane * 4);
    const float4 ad = *(const float4*)(a_dst + h * 128 + lane * 4);
    float s = v.x * as.x + v.y * as.y + v.z * as.z + v.w * as.w;
    float d = v.x * ad.x + v.y * ad.y + v.z * ad.z + v.w * ad.w;
    for (int o = 16; o; o >>= 1) {
        s += __shfl_xor_sync(0xffffffffu, s, o);
        d += __shfl_xor_sync(0xffffffffu, d, o);
    }
    if (lane == 0) { g_as1[n * 8 + h] = s; g_ad1[n * 8 + h] = d; }
}

__global__ void k_alpha2(const float* __restrict__ a_src,
                         const float* __restrict__ a_dst) {
    int n = blockIdx.x * (blockDim.x >> 5) + (threadIdx.x >> 5);
    if (n >= NN) return;
    int lane = threadIdx.x & 31;
    const float4 v  = *(const float4*)(g_xl2 + (size_t)n * 128 + lane * 4);
    const float4 as = *(const float4*)(a_src + lane * 4);
    const float4 ad = *(const float4*)(a_dst + lane * 4);
    float s = v.x * as.x + v.y * as.y + v.z * as.z + v.w * as.w;
    float d = v.x * ad.x + v.y * ad.y + v.z * ad.z + v.w * ad.w;
    for (int o = 16; o; o >>= 1) {
        s += __shfl_xor_sync(0xffffffffu, s, o);
        d += __shfl_xor_sync(0xffffffffu, d, o);
    }
    if (lane == 0) { g_as2[n] = s; g_ad2[n] = d; }
}

// ---------------- fused GAT gather (softmax + aggregate + bias + ELU) ----------
__global__ void k_gather1(const float* __restrict__ bias) {
    int n = blockIdx.x;
    int h = threadIdx.x >> 5;
    int lane = threadIdx.x & 31;
    int beg = g_off[n], end = g_off[n + 1];
    float adv = g_ad1[n * 8 + h];

    float m = -INFINITY;
    for (int i = beg + lane; i < end; i += 32) {
        int s = g_csr_src[i];
        m = fmaxf(m, lrelu(g_as1[s * 8 + h] + adv));
    }
    for (int o = 16; o; o >>= 1) m = fmaxf(m, __shfl_xor_sync(0xffffffffu, m, o));

    float4 acc = make_float4(0.f, 0.f, 0.f, 0.f);
    float denom = 0.f;
    const float* xh = g_xl1 + h * 128 + lane * 4;
    for (int i = beg; i < end; i++) {
        int s = g_csr_src[i];
        float e = lrelu(g_as1[s * 8 + h] + adv);
        float w = __expf(e - m);
        denom += w;
        float4 v = *(const float4*)(xh + (size_t)s * 1024);
        acc.x += w * v.x; acc.y += w * v.y; acc.z += w * v.z; acc.w += w * v.w;
    }
    float inv = 1.f / (denom + 1e-16f);
    int c = h * 128 + lane * 4;
    float4 b = *(const float4*)(bias + c);
    float4 o;
    o.x = elu(acc.x * inv + b.x);
    o.y = elu(acc.y * inv + b.y);
    o.z = elu(acc.z * inv + b.z);
    o.w = elu(acc.w * inv + b.w);
    *(float4*)(g_h1 + (size_t)n * 1024 + c) = o;
}

__global__ void k_gather2(const float* __restrict__ bias) {
    int n = blockIdx.x * (blockDim.x >> 5) + (threadIdx.x >> 5);
    if (n >= NN) return;
    int lane = threadIdx.x & 31;
    int beg = g_off[n], end = g_off[n + 1];
    float adv = g_ad2[n];

    float m = -INFINITY;
    for (int i = beg + lane; i < end; i += 32)
        m = fmaxf(m, lrelu(g_as2[g_csr_src[i]] + adv));
    for (int o = 16; o; o >>= 1) m = fmaxf(m, __shfl_xor_sync(0xffffffffu, m, o));

    float4 acc = make_float4(0.f, 0.f, 0.f, 0.f);
    float denom = 0.f;
    for (int i = beg; i < end; i++) {
        int s = g_csr_src[i];
        float w = __expf(lrelu(g_as2[s] + adv) - m);
        denom += w;
        float4 v = *(const float4*)(g_xl2 + (size_t)s * 128 + lane * 4);
        acc.x += w * v.x; acc.y += w * v.y; acc.z += w * v.z; acc.w += w * v.w;
    }
    float inv = 1.f / (denom + 1e-16f);
    float4 b = *(const float4*)(bias + lane * 4);
    float4 o;
    o.x = elu(acc.x * inv + b.x);
    o.y = elu(acc.y * inv + b.y);
    o.z = elu(acc.z * inv + b.z);
    o.w = elu(acc.w * inv + b.w);
    *(float4*)(g_h2 + (size_t)n * 128 + lane * 4) = o;
}

// ---------------- global mean pool (batch int32, sorted) ----------------
__global__ void k_pool(const int* __restrict__ batch) {
    int g = blockIdx.x;
    __shared__ int s_lo, s_hi;
    if (threadIdx.x == 0) {
        int lo = 0, hi = NN;
        while (lo < hi) { int mid = (lo + hi) >> 1; if (batch[mid] < g) lo = mid + 1; else hi = mid; }
        s_lo = lo;
        lo = 0; hi = NN;
        while (lo < hi) { int mid = (lo + hi) >> 1; if (batch[mid] < g + 1) lo = mid + 1; else hi = mid; }
        s_hi = lo;
    }
    __syncthreads();
    int lo = s_lo, hi = s_hi;
    int c = threadIdx.x;
    float acc = 0.f;
    for (int n = lo; n < hi; n++) acc += g_h2[(size_t)n * 128 + c];
    float cnt = (float)(hi - lo);
    g_pooled[g * 128 + c] = acc / fmaxf(cnt, 1.f);
}

// ---------------- final MLP ----------------
__global__ void k_mlp(const float* __restrict__ lin1_w, const float* __restrict__ lin1_b,
                      const float* __restrict__ lin2_w, const float* __restrict__ lin2_b,
                      float* __restrict__ out) {
    int g = blockIdx.x;
    int t = threadIdx.x;
    __shared__ float sp[128];
    __shared__ float sz[128];
    sp[t] = g_pooled[g * 128 + t];
    __syncthreads();
    float acc = lin1_b[t];
    #pragma unroll 8
    for (int c = 0; c < 128; c++) acc += sp[c] * lin1_w[c * 128 + t];
    sz[t] = fmaxf(acc, 0.f) * lin2_w[t];
    __syncthreads();
    for (int o = 64; o; o >>= 1) {
        if (t < o) sz[t] += sz[t + o];
        __syncthreads();
    }
    if (t == 0) out[g] = sz[0] + lin2_b[0];
}

// ---------------- launch ----------------
extern "C" void kernel_launch(void* const* d_in, const int* in_sizes, int n_in,
                              void* d_out, int out_size) {
    const float* x      = (const float*)d_in[0];
    const int*   ei     = (const int*)d_in[1];     // int32 (JAX x64 disabled)
    const int*   batch  = (const int*)d_in[2];
    const float* W1     = (const float*)d_in[3];
    const float* a_src1 = (const float*)d_in[4];
    const float* a_dst1 = (const float*)d_in[5];
    const float* b1     = (const float*)d_in[6];
    const float* W2     = (const float*)d_in[7];
    const float* a_src2 = (const float*)d_in[8];
    const float* a_dst2 = (const float*)d_in[9];
    const float* b2     = (const float*)d_in[10];
    const float* lin1_w = (const float*)d_in[11];
    const float* lin1_b = (const float*)d_in[12];
    const float* lin2_w = (const float*)d_in[13];
    const float* lin2_b = (const float*)d_in[14];
    float* out = (float*)d_out;

    int E0 = in_sizes[1] / 2;       // 320000
    int E  = E0 + NN;               // 330000

    // CSR build
    k_init_counts<<<(NN + 255) / 256, 256>>>();
    k_count<<<(E + 255) / 256, 256>>>(ei, E0);
    k_scan<<<1, 1024>>>();
    k_scatter<<<(E + 255) / 256, 256>>>(ei, E0);

    // layer 1: xl1 = x @ W1   (M=10000, N=1024, K=128)
    {
        dim3 grid(1024 / 64, (NN + 127) / 128);
        k_mma<<<grid, 256>>>(x, W1, NN, 1024, 128, 0, 0);
    }
    k_alpha1<<<NN, 256>>>(a_src1, a_dst1);
    k_gather1<<<NN, 256>>>(b1);

    // layer 2: xl2 = h1 @ W2  (M=10000, N=128, K=1024)
    {
        dim3 grid(128 / 64, (NN + 127) / 128);
        k_mma<<<grid, 256>>>(x /*unused*/, W2, NN, 128, 1024, 1, 1);
    }
    k_alpha2<<<(NN * 32 + 255) / 256, 256>>>(a_src2, a_dst2);
    k_gather2<<<(NN * 32 + 255) / 256, 256>>>(b2);

    // pool + MLP head
    k_pool<<<NG, 128>>>(batch);
    k_mlp<<<NG, 128>>>(lin1_w, lin1_b, lin2_w, lin2_b, out);
}

// round 6
// speedup vs baseline: 1.0835x; 1.0835x over previous
#include <cuda_runtime.h>
#include <math.h>

#define NN      10000
#define NG      64
#define ET      330000   // E0 + self loops

// ---------------- device scratch (static; no allocation) ----------------
__device__ float g_xl1[NN * 1024];   // layer1: per-head input-space aggregate [N, 8*128]
__device__ float g_h1 [NN * 1024];   // layer1 output   [N, 1024]
__device__ float g_as1[NN * 8];
__device__ float g_ad1[NN * 8];
__device__ float g_vas[128 * 8];     // W1 . a_src1  [K=128, H=8]
__device__ float g_vad[128 * 8];     // W1 . a_dst1
__device__ float g_xl2[NN * 128];    // h1 @ W2
__device__ float g_as2[NN];
__device__ float g_ad2[NN];
__device__ float g_h2 [NN * 128];
__device__ float g_pooled[NG * 128];
__device__ int   g_cnt[NN];
__device__ int   g_cur[NN];
__device__ int   g_off[NN + 1];
__device__ int   g_csr_src[ET];

// ---------------- helpers ----------------
__device__ __forceinline__ void get_edge(const int* ei, int E0, int e,
                                         int& s, int& d) {
    if (e < E0) { s = ei[e]; d = ei[E0 + e]; }
    else        { s = e - E0; d = e - E0; }
}

__device__ __forceinline__ float lrelu(float x) { return x > 0.f ? x : 0.2f * x; }
__device__ __forceinline__ float elu(float x)   { return x > 0.f ? x : expm1f(x); }

// ---------------- CSR build ----------------
__global__ void k_init_counts() {
    int i = blockIdx.x * blockDim.x + threadIdx.x;
    if (i < NN) { g_cnt[i] = 0; g_cur[i] = 0; }
}

__global__ void k_count(const int* ei, int E0) {
    int e = blockIdx.x * blockDim.x + threadIdx.x;
    if (e >= E0 + NN) return;
    int s, d; get_edge(ei, E0, e, s, d);
    if ((unsigned)s >= NN || (unsigned)d >= NN) return;
    atomicAdd(&g_cnt[d], 1);
}

__global__ void k_scan() {
    __shared__ int part[1024];
    const int CH = 10;
    int tid = threadIdx.x;
    int local[CH];
    int s = 0;
    #pragma unroll
    for (int i = 0; i < CH; i++) {
        int idx = tid * CH + i;
        int v = (idx < NN) ? g_cnt[idx] : 0;
        local[i] = s; s += v;
    }
    part[tid] = s;
    __syncthreads();
    for (int o = 1; o < 1024; o <<= 1) {
        int v = (tid >= o) ? part[tid - o] : 0;
        __syncthreads();
        part[tid] += v;
        __syncthreads();
    }
    int pre = tid ? part[tid - 1] : 0;
    #pragma unroll
    for (int i = 0; i < CH; i++) {
        int idx = tid * CH + i;
        if (idx < NN) g_off[idx] = pre + local[i];
    }
    if (tid == 1023) g_off[NN] = part[1023];
}

__global__ void k_scatter(const int* ei, int E0) {
    int e = blockIdx.x * blockDim.x + threadIdx.x;
    if (e >= E0 + NN) return;
    int s, d; get_edge(ei, E0, e, s, d);
    if ((unsigned)s >= NN || (unsigned)d >= NN) return;
    int pos = atomicAdd(&g_cur[d], 1);
    g_csr_src[g_off[d] + pos] = s;
}

// ---------------- va = W1 . a  (per head) ----------------
// g_vas[k*8+h] = sum_c W1[k, h*128+c] * a_src1[h, c]
__global__ void k_va(const float* __restrict__ W1, const float* __restrict__ as,
                     const float* __restrict__ ad) {
    int t = blockIdx.x * blockDim.x + threadIdx.x;   // 0..1023
    if (t >= 1024) return;
    int k = t >> 3, h = t & 7;
    float ss = 0.f, dd = 0.f;
    const float* wrow = W1 + (size_t)k * 1024 + h * 128;
    const float* asr = as + h * 128;
    const float* adr = ad + h * 128;
    #pragma unroll 8
    for (int c = 0; c < 128; c++) { float w = wrow[c]; ss += w * asr[c]; dd += w * adr[c]; }
    g_vas[k * 8 + h] = ss;
    g_vad[k * 8 + h] = dd;
}

// ---------------- layer1 logits: as1[n,h] = x[n] . vas[:,h] ----------------
__global__ void k_alpha1n(const float* __restrict__ x) {
    int n = blockIdx.x * 8 + (threadIdx.x >> 5);
    if (n >= NN) return;
    int lane = threadIdx.x & 31;
    float4 xv = *(const float4*)(x + (size_t)n * 128 + lane * 4);
    float xa[4] = {xv.x, xv.y, xv.z, xv.w};
    float s[8] = {0,0,0,0,0,0,0,0}, d[8] = {0,0,0,0,0,0,0,0};
    #pragma unroll
    for (int j = 0; j < 4; j++) {
        int k = lane * 4 + j;
        float xj = xa[j];
        float4 v0 = *(const float4*)(g_vas + k * 8);
        float4 v1 = *(const float4*)(g_vas + k * 8 + 4);
        float4 w0 = *(const float4*)(g_vad + k * 8);
        float4 w1 = *(const float4*)(g_vad + k * 8 + 4);
        s[0] += xj * v0.x; s[1] += xj * v0.y; s[2] += xj * v0.z; s[3] += xj * v0.w;
        s[4] += xj * v1.x; s[5] += xj * v1.y; s[6] += xj * v1.z; s[7] += xj * v1.w;
        d[0] += xj * w0.x; d[1] += xj * w0.y; d[2] += xj * w0.z; d[3] += xj * w0.w;
        d[4] += xj * w1.x; d[5] += xj * w1.y; d[6] += xj * w1.z; d[7] += xj * w1.w;
    }
    #pragma unroll
    for (int hh = 0; hh < 8; hh++)
        for (int o = 16; o; o >>= 1) {
            s[hh] += __shfl_xor_sync(0xffffffffu, s[hh], o);
            d[hh] += __shfl_xor_sync(0xffffffffu, d[hh], o);
        }
    if (lane == 0) {
        #pragma unroll
        for (int hh = 0; hh < 8; hh++) {
            g_as1[n * 8 + hh] = s[hh];
            g_ad1[n * 8 + hh] = d[hh];
        }
    }
}

// ---------------- layer1 gather in INPUT space ----------------
// block per dst node, 128 threads = channels; 8 head accumulators per thread.
// writes g_xl1[n*1024 + h*128 + c] = (sum_s w_h x[s][c]) / denom_h
__global__ void k_gather1n(const float* __restrict__ x) {
    __shared__ float s_m[8], s_inv[8], s_ad[8];
    __shared__ float red_m[128], red_s[128];
    __shared__ float ws[32][9];
    __shared__ int   ssrc[32];

    int n = blockIdx.x;
    int t = threadIdx.x;
    int beg = g_off[n], end = g_off[n + 1];

    // ---- pass 1: online (max, sum) per head ----
    int h = t & 7, slot = t >> 3;
    float advh = g_ad1[n * 8 + h];
    if (t < 8) s_ad[t] = advh;
    float m = -INFINITY, ssum = 0.f;
    for (int i = beg + slot; i < end; i += 16) {
        int s = g_csr_src[i];
        float e = lrelu(g_as1[s * 8 + h] + advh);
        if (e > m) { ssum = ssum * __expf(m - e) + 1.f; m = e; }
        else        ssum += __expf(e - m);
    }
    red_m[t] = m; red_s[t] = ssum;
    __syncthreads();
    if (t < 8) {
        float M = -INFINITY;
        for (int i = t; i < 128; i += 8) M = fmaxf(M, red_m[i]);
        float S = 0.f;
        for (int i = t; i < 128; i += 8) {
            float mi = red_m[i];
            if (mi > -INFINITY) S += red_s[i] * __expf(mi - M);
        }
        s_m[t] = M;
        s_inv[t] = 1.f / (S + 1e-16f);
    }
    __syncthreads();

    // ---- pass 2: chunked weighted accumulation ----
    int lane = t & 31, wid = t >> 5;
    float acc[8] = {0,0,0,0,0,0,0,0};
    for (int base = beg; base < end; base += 32) {
        int cnt = min(32, end - base);
        if (wid == 0 && lane < cnt) {
            int s = g_csr_src[base + lane];
            ssrc[lane] = s;
            float4 a0 = *(const float4*)(g_as1 + s * 8);
            float4 a1 = *(const float4*)(g_as1 + s * 8 + 4);
            ws[lane][0] = __expf(lrelu(a0.x + s_ad[0]) - s_m[0]);
            ws[lane][1] = __expf(lrelu(a0.y + s_ad[1]) - s_m[1]);
            ws[lane][2] = __expf(lrelu(a0.z + s_ad[2]) - s_m[2]);
            ws[lane][3] = __expf(lrelu(a0.w + s_ad[3]) - s_m[3]);
            ws[lane][4] = __expf(lrelu(a1.x + s_ad[4]) - s_m[4]);
            ws[lane][5] = __expf(lrelu(a1.y + s_ad[5]) - s_m[5]);
            ws[lane][6] = __expf(lrelu(a1.z + s_ad[6]) - s_m[6]);
            ws[lane][7] = __expf(lrelu(a1.w + s_ad[7]) - s_m[7]);
        }
        __syncthreads();
        #pragma unroll 4
        for (int i = 0; i < cnt; i++) {
            float xv = x[(size_t)ssrc[i] * 128 + t];
            #pragma unroll
            for (int hh = 0; hh < 8; hh++) acc[hh] += ws[i][hh] * xv;
        }
        __syncthreads();
    }

    float* dst = g_xl1 + (size_t)n * 1024 + t;
    #pragma unroll
    for (int hh = 0; hh < 8; hh++) dst[hh * 128] = acc[hh] * s_inv[hh];
}

// ---------------- SIMT SGEMM (generalized): C = A @ B, optional bias+ELU -------
// 64x64 tile, BK=16, 256 threads, 4x4 microtile.
// a_sel: 0 -> Aext, 1 -> g_xl1, 2 -> g_h1.   c_sel: 0 -> g_xl1, 1 -> g_xl2, 2 -> g_h1.
// Per-z head offset hs applied to A (intra-row), B (col), C (intra-row), bias.
__global__ void k_sgemm(const float* __restrict__ Aext, const float* __restrict__ Bext,
                        const float* __restrict__ bias,
                        int M, int N, int K, int lda, int ldb, int ldc,
                        int a_sel, int c_sel, int hs, int do_elu) {
    int z = blockIdx.z;
    const float* A = (a_sel == 0 ? Aext : a_sel == 1 ? (const float*)g_xl1 : (const float*)g_h1) + z * hs;
    const float* B = Bext + z * hs;
    float* C = (c_sel == 0 ? g_xl1 : c_sel == 1 ? g_xl2 : g_h1) + z * hs;

    __shared__ float As[16][64];
    __shared__ float Bs[16][64];
    int brow = blockIdx.y * 64;
    int bcol = blockIdx.x * 64;
    int tid = threadIdx.x;
    int tx = tid & 15, ty = tid >> 4;

    float acc[4][4] = {};

    for (int k0 = 0; k0 < K; k0 += 16) {
        {
            int mr = tid >> 2;
            int kk = (tid & 3) * 4;
            int row = brow + mr;
            float4 v = make_float4(0.f, 0.f, 0.f, 0.f);
            if (row < M) v = *(const float4*)(A + (size_t)row * lda + k0 + kk);
            As[kk + 0][mr] = v.x; As[kk + 1][mr] = v.y;
            As[kk + 2][mr] = v.z; As[kk + 3][mr] = v.w;
        }
        {
            int kk  = tid >> 4;
            int col = (tid & 15) * 4;
            float4 v = *(const float4*)(B + (size_t)(k0 + kk) * ldb + bcol + col);
            Bs[kk][col + 0] = v.x; Bs[kk][col + 1] = v.y;
            Bs[kk][col + 2] = v.z; Bs[kk][col + 3] = v.w;
        }
        __syncthreads();
        #pragma unroll
        for (int kk = 0; kk < 16; kk++) {
            float a[4], b[4];
            #pragma unroll
            for (int i = 0; i < 4; i++) a[i] = As[kk][ty * 4 + i];
            #pragma unroll
            for (int j = 0; j < 4; j++) b[j] = Bs[kk][tx * 4 + j];
            #pragma unroll
            for (int i = 0; i < 4; i++)
                #pragma unroll
                for (int j = 0; j < 4; j++)
                    acc[i][j] += a[i] * b[j];
        }
        __syncthreads();
    }

    float4 bv = make_float4(0.f, 0.f, 0.f, 0.f);
    if (do_elu) bv = *(const float4*)(bias + z * hs + bcol + tx * 4);
    #pragma unroll
    for (int i = 0; i < 4; i++) {
        int row = brow + ty * 4 + i;
        if (row >= M) continue;
        float4 v = make_float4(acc[i][0], acc[i][1], acc[i][2], acc[i][3]);
        if (do_elu) {
            v.x = elu(v.x + bv.x); v.y = elu(v.y + bv.y);
            v.z = elu(v.z + bv.z); v.w = elu(v.w + bv.w);
        }
        *(float4*)(C + (size_t)row * ldc + bcol + tx * 4) = v;
    }
}

// ---------------- layer2 logits ----------------
__global__ void k_alpha2(const float* __restrict__ a_src,
                         const float* __restrict__ a_dst) {
    int n = blockIdx.x * (blockDim.x >> 5) + (threadIdx.x >> 5);
    if (n >= NN) return;
    int lane = threadIdx.x & 31;
    const float4 v  = *(const float4*)(g_xl2 + (size_t)n * 128 + lane * 4);
    const float4 as = *(const float4*)(a_src + lane * 4);
    const float4 ad = *(const float4*)(a_dst + lane * 4);
    float s = v.x * as.x + v.y * as.y + v.z * as.z + v.w * as.w;
    float d = v.x * ad.x + v.y * ad.y + v.z * ad.z + v.w * ad.w;
    for (int o = 16; o; o >>= 1) {
        s += __shfl_xor_sync(0xffffffffu, s, o);
        d += __shfl_xor_sync(0xffffffffu, d, o);
    }
    if (lane == 0) { g_as2[n] = s; g_ad2[n] = d; }
}

// ---------------- layer2 gather (single head) ----------------
__global__ void k_gather2(const float* __restrict__ bias) {
    int n = blockIdx.x * (blockDim.x >> 5) + (threadIdx.x >> 5);
    if (n >= NN) return;
    int lane = threadIdx.x & 31;
    int beg = g_off[n], end = g_off[n + 1];
    float adv = g_ad2[n];

    float m = -INFINITY;
    for (int i = beg + lane; i < end; i += 32)
        m = fmaxf(m, lrelu(g_as2[g_csr_src[i]] + adv));
    for (int o = 16; o; o >>= 1) m = fmaxf(m, __shfl_xor_sync(0xffffffffu, m, o));

    float4 acc = make_float4(0.f, 0.f, 0.f, 0.f);
    float denom = 0.f;
    for (int i = beg; i < end; i++) {
        int s = g_csr_src[i];
        float w = __expf(lrelu(g_as2[s] + adv) - m);
        denom += w;
        float4 v = *(const float4*)(g_xl2 + (size_t)s * 128 + lane * 4);
        acc.x += w * v.x; acc.y += w * v.y; acc.z += w * v.z; acc.w += w * v.w;
    }
    float inv = 1.f / (denom + 1e-16f);
    float4 b = *(const float4*)(bias + lane * 4);
    float4 o;
    o.x = elu(acc.x * inv + b.x);
    o.y = elu(acc.y * inv + b.y);
    o.z = elu(acc.z * inv + b.z);
    o.w = elu(acc.w * inv + b.w);
    *(float4*)(g_h2 + (size_t)n * 128 + lane * 4) = o;
}

// ---------------- global mean pool ----------------
__global__ void k_pool(const int* __restrict__ batch) {
    int g = blockIdx.x;
    __shared__ int s_lo, s_hi;
    if (threadIdx.x == 0) {
        int lo = 0, hi = NN;
        while (lo < hi) { int mid = (lo + hi) >> 1; if (batch[mid] < g) lo = mid + 1; else hi = mid; }
        s_lo = lo;
        lo = 0; hi = NN;
        while (lo < hi) { int mid = (lo + hi) >> 1; if (batch[mid] < g + 1) lo = mid + 1; else hi = mid; }
        s_hi = lo;
    }
    __syncthreads();
    int lo = s_lo, hi = s_hi;
    int c = threadIdx.x;
    float acc = 0.f;
    for (int n = lo; n < hi; n++) acc += g_h2[(size_t)n * 128 + c];
    float cnt = (float)(hi - lo);
    g_pooled[g * 128 + c] = acc / fmaxf(cnt, 1.f);
}

// ---------------- final MLP ----------------
__global__ void k_mlp(const float* __restrict__ lin1_w, const float* __restrict__ lin1_b,
                      const float* __restrict__ lin2_w, const float* __restrict__ lin2_b,
                      float* __restrict__ out) {
    int g = blockIdx.x;
    int t = threadIdx.x;
    __shared__ float sp[128];
    __shared__ float sz[128];
    sp[t] = g_pooled[g * 128 + t];
    __syncthreads();
    float acc = lin1_b[t];
    #pragma unroll 8
    for (int c = 0; c < 128; c++) acc += sp[c] * lin1_w[c * 128 + t];
    sz[t] = fmaxf(acc, 0.f) * lin2_w[t];
    __syncthreads();
    for (int o = 64; o; o >>= 1) {
        if (t < o) sz[t] += sz[t + o];
        __syncthreads();
    }
    if (t == 0) out[g] = sz[0] + lin2_b[0];
}

// ---------------- launch ----------------
extern "C" void kernel_launch(void* const* d_in, const int* in_sizes, int n_in,
                              void* d_out, int out_size) {
    const float* x      = (const float*)d_in[0];
    const int*   ei     = (const int*)d_in[1];
    const int*   batch  = (const int*)d_in[2];
    const float* W1     = (const float*)d_in[3];
    const float* a_src1 = (const float*)d_in[4];
    const float* a_dst1 = (const float*)d_in[5];
    const float* b1     = (const float*)d_in[6];
    const float* W2     = (const float*)d_in[7];
    const float* a_src2 = (const float*)d_in[8];
    const float* a_dst2 = (const float*)d_in[9];
    const float* b2     = (const float*)d_in[10];
    const float* lin1_w = (const float*)d_in[11];
    const float* lin1_b = (const float*)d_in[12];
    const float* lin2_w = (const float*)d_in[13];
    const float* lin2_b = (const float*)d_in[14];
    float* out = (float*)d_out;

    int E0 = in_sizes[1] / 2;       // 320000
    int E  = E0 + NN;               // 330000

    // CSR build
    k_init_counts<<<(NN + 255) / 256, 256>>>();
    k_count<<<(E + 255) / 256, 256>>>(ei, E0);
    k_scan<<<1, 1024>>>();
    k_scatter<<<(E + 255) / 256, 256>>>(ei, E0);

    // layer 1 (input-space aggregation)
    k_va<<<4, 256>>>(W1, a_src1, a_dst1);
    k_alpha1n<<<(NN + 7) / 8, 256>>>(x);
    k_gather1n<<<NN, 128>>>(x);
    // h1[n, h*128:+128] = elu( agg[n,h] @ W1[:, h*128:+128] + b1 )  (8 heads via z)
    {
        dim3 grid(2, (NN + 63) / 64, 8);
        k_sgemm<<<grid, 256>>>(nullptr, W1, b1, NN, 128, 128,
                               1024, 1024, 1024, /*a_sel=*/1, /*c_sel=*/2,
                               /*hs=*/128, /*do_elu=*/1);
    }

    // layer 2: xl2 = h1 @ W2  (M=10000, N=128, K=1024)
    {
        dim3 grid(2, (NN + 63) / 64, 1);
        k_sgemm<<<grid, 256>>>(nullptr, W2, nullptr, NN, 128, 1024,
                               1024, 128, 128, /*a_sel=*/2, /*c_sel=*/1,
                               /*hs=*/0, /*do_elu=*/0);
    }
    k_alpha2<<<(NN * 32 + 255) / 256, 256>>>(a_src2, a_dst2);
    k_gather2<<<(NN * 32 + 255) / 256, 256>>>(b2);

    // pool + MLP head
    k_pool<<<NG, 128>>>(batch);
    k_mlp<<<NG, 128>>>(lin1_w, lin1_b, lin2_w, lin2_b, out);
}

// round 7
// speedup vs baseline: 1.4022x; 1.2941x over previous
#include <cuda_runtime.h>
#include <math.h>

#define NN      10000
#define NG      64
#define ET      330000   // E0 + self loops
#define KSPLIT  4

// ---------------- device scratch (static; no allocation) ----------------
__device__ float g_xl1[NN * 1024];   // layer1 per-head input-space aggregate [N, 8*128]
__device__ float g_h1 [NN * 1024];   // layer1 output   [N, 1024]
__device__ float g_as1[NN * 8];
__device__ float g_ad1[NN * 8];
__device__ float g_vas[128 * 8];
__device__ float g_vad[128 * 8];
__device__ float g_xl2p[KSPLIT * NN * 128];  // layer2 GEMM partials
__device__ float g_xl2[NN * 128];
__device__ float g_as2[NN];
__device__ float g_ad2[NN];
__device__ float g_h2 [NN * 128];
__device__ float g_pooled[NG * 128];
__device__ int   g_cnt[NN];
__device__ int   g_cur[NN];
__device__ int   g_off[NN + 1];
__device__ int   g_csr_src[ET];

// ---------------- helpers ----------------
__device__ __forceinline__ void get_edge(const int* ei, int E0, int e,
                                         int& s, int& d) {
    if (e < E0) { s = ei[e]; d = ei[E0 + e]; }
    else        { s = e - E0; d = e - E0; }
}

__device__ __forceinline__ float lrelu(float x) { return x > 0.f ? x : 0.2f * x; }
__device__ __forceinline__ float elu(float x)   { return x > 0.f ? x : expm1f(x); }

__device__ __forceinline__ float tf32r(float x) {
    unsigned u;
    asm("cvt.rna.tf32.f32 %0, %1;" : "=r"(u) : "f"(x));
    return __uint_as_float(u);
}

__device__ __forceinline__ void mma_tf32(float* d, const unsigned* a, const unsigned* b) {
    asm volatile(
        "mma.sync.aligned.m16n8k8.row.col.f32.tf32.tf32.f32 "
        "{%0,%1,%2,%3},{%4,%5,%6,%7},{%8,%9},{%0,%1,%2,%3};"
        : "+f"(d[0]), "+f"(d[1]), "+f"(d[2]), "+f"(d[3])
        : "r"(a[0]), "r"(a[1]), "r"(a[2]), "r"(a[3]), "r"(b[0]), "r"(b[1]));
}

// ---------------- CSR build ----------------
__global__ void k_init_counts() {
    int i = blockIdx.x * blockDim.x + threadIdx.x;
    if (i < NN) { g_cnt[i] = 0; g_cur[i] = 0; }
}

__global__ void k_count(const int* ei, int E0) {
    int e = blockIdx.x * blockDim.x + threadIdx.x;
    if (e >= E0 + NN) return;
    int s, d; get_edge(ei, E0, e, s, d);
    if ((unsigned)s >= NN || (unsigned)d >= NN) return;
    atomicAdd(&g_cnt[d], 1);
}

__global__ void k_scan() {
    __shared__ int part[1024];
    const int CH = 10;
    int tid = threadIdx.x;
    int local[CH];
    int s = 0;
    #pragma unroll
    for (int i = 0; i < CH; i++) {
        int idx = tid * CH + i;
        int v = (idx < NN) ? g_cnt[idx] : 0;
        local[i] = s; s += v;
    }
    part[tid] = s;
    __syncthreads();
    for (int o = 1; o < 1024; o <<= 1) {
        int v = (tid >= o) ? part[tid - o] : 0;
        __syncthreads();
        part[tid] += v;
        __syncthreads();
    }
    int pre = tid ? part[tid - 1] : 0;
    #pragma unroll
    for (int i = 0; i < CH; i++) {
        int idx = tid * CH + i;
        if (idx < NN) g_off[idx] = pre + local[i];
    }
    if (tid == 1023) g_off[NN] = part[1023];
}

__global__ void k_scatter(const int* ei, int E0) {
    int e = blockIdx.x * blockDim.x + threadIdx.x;
    if (e >= E0 + NN) return;
    int s, d; get_edge(ei, E0, e, s, d);
    if ((unsigned)s >= NN || (unsigned)d >= NN) return;
    int pos = atomicAdd(&g_cur[d], 1);
    g_csr_src[g_off[d] + pos] = s;
}

// ---------------- va = W1 . a  (per head) ----------------
__global__ void k_va(const float* __restrict__ W1, const float* __restrict__ as,
                     const float* __restrict__ ad) {
    int t = blockIdx.x * blockDim.x + threadIdx.x;
    if (t >= 1024) return;
    int k = t >> 3, h = t & 7;
    float ss = 0.f, dd = 0.f;
    const float* wrow = W1 + (size_t)k * 1024 + h * 128;
    const float* asr = as + h * 128;
    const float* adr = ad + h * 128;
    #pragma unroll 8
    for (int c = 0; c < 128; c++) { float w = wrow[c]; ss += w * asr[c]; dd += w * adr[c]; }
    g_vas[k * 8 + h] = ss;
    g_vad[k * 8 + h] = dd;
}

// ---------------- layer1 logits ----------------
__global__ void k_alpha1n(const float* __restrict__ x) {
    int n = blockIdx.x * 8 + (threadIdx.x >> 5);
    if (n >= NN) return;
    int lane = threadIdx.x & 31;
    float4 xv = *(const float4*)(x + (size_t)n * 128 + lane * 4);
    float xa[4] = {xv.x, xv.y, xv.z, xv.w};
    float s[8] = {0,0,0,0,0,0,0,0}, d[8] = {0,0,0,0,0,0,0,0};
    #pragma unroll
    for (int j = 0; j < 4; j++) {
        int k = lane * 4 + j;
        float xj = xa[j];
        float4 v0 = *(const float4*)(g_vas + k * 8);
        float4 v1 = *(const float4*)(g_vas + k * 8 + 4);
        float4 w0 = *(const float4*)(g_vad + k * 8);
        float4 w1 = *(const float4*)(g_vad + k * 8 + 4);
        s[0] += xj * v0.x; s[1] += xj * v0.y; s[2] += xj * v0.z; s[3] += xj * v0.w;
        s[4] += xj * v1.x; s[5] += xj * v1.y; s[6] += xj * v1.z; s[7] += xj * v1.w;
        d[0] += xj * w0.x; d[1] += xj * w0.y; d[2] += xj * w0.z; d[3] += xj * w0.w;
        d[4] += xj * w1.x; d[5] += xj * w1.y; d[6] += xj * w1.z; d[7] += xj * w1.w;
    }
    #pragma unroll
    for (int hh = 0; hh < 8; hh++)
        for (int o = 16; o; o >>= 1) {
            s[hh] += __shfl_xor_sync(0xffffffffu, s[hh], o);
            d[hh] += __shfl_xor_sync(0xffffffffu, d[hh], o);
        }
    if (lane == 0) {
        #pragma unroll
        for (int hh = 0; hh < 8; hh++) {
            g_as1[n * 8 + hh] = s[hh];
            g_ad1[n * 8 + hh] = d[hh];
        }
    }
}

// ---------------- layer1 gather (input space) ----------------
__global__ void k_gather1n(const float* __restrict__ x) {
    __shared__ float s_m[8], s_inv[8], s_ad[8];
    __shared__ float red_m[128], red_s[128];
    __shared__ float ws[32][9];
    __shared__ int   ssrc[32];

    int n = blockIdx.x;
    int t = threadIdx.x;
    int beg = g_off[n], end = g_off[n + 1];

    int h = t & 7, slot = t >> 3;
    float advh = g_ad1[n * 8 + h];
    if (t < 8) s_ad[t] = advh;
    float m = -INFINITY, ssum = 0.f;
    for (int i = beg + slot; i < end; i += 16) {
        int s = g_csr_src[i];
        float e = lrelu(g_as1[s * 8 + h] + advh);
        if (e > m) { ssum = ssum * __expf(m - e) + 1.f; m = e; }
        else        ssum += __expf(e - m);
    }
    red_m[t] = m; red_s[t] = ssum;
    __syncthreads();
    if (t < 8) {
        float M = -INFINITY;
        for (int i = t; i < 128; i += 8) M = fmaxf(M, red_m[i]);
        float S = 0.f;
        for (int i = t; i < 128; i += 8) {
            float mi = red_m[i];
            if (mi > -INFINITY) S += red_s[i] * __expf(mi - M);
        }
        s_m[t] = M;
        s_inv[t] = 1.f / (S + 1e-16f);
    }
    __syncthreads();

    int lane = t & 31, wid = t >> 5;
    float acc[8] = {0,0,0,0,0,0,0,0};
    for (int base = beg; base < end; base += 32) {
        int cnt = min(32, end - base);
        if (wid == 0 && lane < cnt) {
            int s = g_csr_src[base + lane];
            ssrc[lane] = s;
            float4 a0 = *(const float4*)(g_as1 + s * 8);
            float4 a1 = *(const float4*)(g_as1 + s * 8 + 4);
            ws[lane][0] = __expf(lrelu(a0.x + s_ad[0]) - s_m[0]);
            ws[lane][1] = __expf(lrelu(a0.y + s_ad[1]) - s_m[1]);
            ws[lane][2] = __expf(lrelu(a0.z + s_ad[2]) - s_m[2]);
            ws[lane][3] = __expf(lrelu(a0.w + s_ad[3]) - s_m[3]);
            ws[lane][4] = __expf(lrelu(a1.x + s_ad[4]) - s_m[4]);
            ws[lane][5] = __expf(lrelu(a1.y + s_ad[5]) - s_m[5]);
            ws[lane][6] = __expf(lrelu(a1.z + s_ad[6]) - s_m[6]);
            ws[lane][7] = __expf(lrelu(a1.w + s_ad[7]) - s_m[7]);
        }
        __syncthreads();
        #pragma unroll 4
        for (int i = 0; i < cnt; i++) {
            float xv = x[(size_t)ssrc[i] * 128 + t];
            #pragma unroll
            for (int hh = 0; hh < 8; hh++) acc[hh] += ws[i][hh] * xv;
        }
        __syncthreads();
    }

    float* dst = g_xl1 + (size_t)n * 1024 + t;
    #pragma unroll
    for (int hh = 0; hh < 8; hh++) dst[hh * 128] = acc[hh] * s_inv[hh];
}

// ---------------- single-pass TF32 tensor-core GEMM ----------------
// Block tile 128m x 64n, BK=16, 256 threads (8 warps: 4m x 2n, warp tile 32x32).
// a_sel: 1 -> g_xl1, 2 -> g_h1.   c_sel: 0 -> g_xl2p, 1 -> g_h1.
// Per-z offsets: A += z*hsA (col), B += z*hsB (element), C += z*hsC, bias += z*hsC.
__global__ void k_mma(const float* __restrict__ Bext, const float* __restrict__ bias,
                      int M, int KC, int lda, int ldb, int ldc,
                      int a_sel, int c_sel, int hsA, long long hsB, long long hsC,
                      int do_elu) {
    int z = blockIdx.z;
    const float* A = (a_sel == 1 ? (const float*)g_xl1 : (const float*)g_h1) + (long long)z * hsA;
    const float* B = Bext + (long long)z * hsB;
    float* C = (c_sel == 0 ? g_xl2p : g_h1) + (long long)z * hsC;

    __shared__ float As[16][132];
    __shared__ float Bs[16][68];

    const int tid  = threadIdx.x;
    const int lane = tid & 31;
    const int wid  = tid >> 5;
    const int tq   = lane >> 2;
    const int t4   = lane & 3;
    const int warp_m = (wid >> 1) * 32;
    const int warp_n = (wid & 1) * 32;

    const int brow = blockIdx.y * 128;
    const int bcol = blockIdx.x * 64;

    const int a_row = tid >> 1;
    const int a_kq  = (tid & 1) * 8;
    const int b_k   = tid >> 4;
    const int b_c   = (tid & 15) * 4;

    float acc[2][4][4];
    #pragma unroll
    for (int i = 0; i < 2; i++)
        #pragma unroll
        for (int j = 0; j < 4; j++)
            #pragma unroll
            for (int r = 0; r < 4; r++) acc[i][j][r] = 0.f;

    for (int k0 = 0; k0 < KC; k0 += 16) {
        {
            int grow = brow + a_row;
            #pragma unroll
            for (int half = 0; half < 2; half++) {
                int kk = a_kq + half * 4;
                float4 v = make_float4(0.f, 0.f, 0.f, 0.f);
                if (grow < M) v = *(const float4*)(A + (size_t)grow * lda + k0 + kk);
                As[kk + 0][a_row] = tf32r(v.x);
                As[kk + 1][a_row] = tf32r(v.y);
                As[kk + 2][a_row] = tf32r(v.z);
                As[kk + 3][a_row] = tf32r(v.w);
            }
        }
        {
            float4 v = *(const float4*)(B + (size_t)(k0 + b_k) * ldb + bcol + b_c);
            Bs[b_k][b_c + 0] = tf32r(v.x);
            Bs[b_k][b_c + 1] = tf32r(v.y);
            Bs[b_k][b_c + 2] = tf32r(v.z);
            Bs[b_k][b_c + 3] = tf32r(v.w);
        }
        __syncthreads();

        #pragma unroll
        for (int ks = 0; ks < 16; ks += 8) {
            unsigned a[2][4];
            #pragma unroll
            for (int fm = 0; fm < 2; fm++) {
                int r = warp_m + fm * 16 + tq;
                a[fm][0] = __float_as_uint(As[ks + t4    ][r    ]);
                a[fm][1] = __float_as_uint(As[ks + t4    ][r + 8]);
                a[fm][2] = __float_as_uint(As[ks + t4 + 4][r    ]);
                a[fm][3] = __float_as_uint(As[ks + t4 + 4][r + 8]);
            }
            unsigned b[4][2];
            #pragma unroll
            for (int fn = 0; fn < 4; fn++) {
                int c = warp_n + fn * 8 + tq;
                b[fn][0] = __float_as_uint(Bs[ks + t4    ][c]);
                b[fn][1] = __float_as_uint(Bs[ks + t4 + 4][c]);
            }
            #pragma unroll
            for (int fm = 0; fm < 2; fm++)
                #pragma unroll
                for (int fn = 0; fn < 4; fn++)
                    mma_tf32(acc[fm][fn], a[fm], b[fn]);
        }
        __syncthreads();
    }

    #pragma unroll
    for (int fm = 0; fm < 2; fm++) {
        int r0 = brow + warp_m + fm * 16 + tq;
        int r1 = r0 + 8;
        #pragma unroll
        for (int fn = 0; fn < 4; fn++) {
            int c = bcol + warp_n + fn * 8 + 2 * t4;
            float2 v0 = make_float2(acc[fm][fn][0], acc[fm][fn][1]);
            float2 v1 = make_float2(acc[fm][fn][2], acc[fm][fn][3]);
            if (do_elu) {
                float2 bv = *(const float2*)(bias + (long long)z * hsC + c);
                v0.x = elu(v0.x + bv.x); v0.y = elu(v0.y + bv.y);
                v1.x = elu(v1.x + bv.x); v1.y = elu(v1.y + bv.y);
            }
            if (r0 < M) *(float2*)(C + (size_t)r0 * ldc + c) = v0;
            if (r1 < M) *(float2*)(C + (size_t)r1 * ldc + c) = v1;
        }
    }
}

// ---------------- layer2: reduce k-split partials + logits ----------------
__global__ void k_alpha2(const float* __restrict__ a_src,
                         const float* __restrict__ a_dst) {
    int n = blockIdx.x * (blockDim.x >> 5) + (threadIdx.x >> 5);
    if (n >= NN) return;
    int lane = threadIdx.x & 31;
    size_t idx = (size_t)n * 128 + lane * 4;
    float4 v = *(const float4*)(g_xl2p + idx);
    #pragma unroll
    for (int z = 1; z < KSPLIT; z++) {
        float4 p = *(const float4*)(g_xl2p + (size_t)z * NN * 128 + idx);
        v.x += p.x; v.y += p.y; v.z += p.z; v.w += p.w;
    }
    *(float4*)(g_xl2 + idx) = v;

    const float4 as = *(const float4*)(a_src + lane * 4);
    const float4 ad = *(const float4*)(a_dst + lane * 4);
    float s = v.x * as.x + v.y * as.y + v.z * as.z + v.w * as.w;
    float d = v.x * ad.x + v.y * ad.y + v.z * ad.z + v.w * ad.w;
    for (int o = 16; o; o >>= 1) {
        s += __shfl_xor_sync(0xffffffffu, s, o);
        d += __shfl_xor_sync(0xffffffffu, d, o);
    }
    if (lane == 0) { g_as2[n] = s; g_ad2[n] = d; }
}

// ---------------- layer2 gather ----------------
__global__ void k_gather2(const float* __restrict__ bias) {
    int n = blockIdx.x * (blockDim.x >> 5) + (threadIdx.x >> 5);
    if (n >= NN) return;
    int lane = threadIdx.x & 31;
    int beg = g_off[n], end = g_off[n + 1];
    float adv = g_ad2[n];

    float m = -INFINITY;
    for (int i = beg + lane; i < end; i += 32)
        m = fmaxf(m, lrelu(g_as2[g_csr_src[i]] + adv));
    for (int o = 16; o; o >>= 1) m = fmaxf(m, __shfl_xor_sync(0xffffffffu, m, o));

    float4 acc = make_float4(0.f, 0.f, 0.f, 0.f);
    float denom = 0.f;
    for (int i = beg; i < end; i++) {
        int s = g_csr_src[i];
        float w = __expf(lrelu(g_as2[s] + adv) - m);
        denom += w;
        float4 v = *(const float4*)(g_xl2 + (size_t)s * 128 + lane * 4);
        acc.x += w * v.x; acc.y += w * v.y; acc.z += w * v.z; acc.w += w * v.w;
    }
    float inv = 1.f / (denom + 1e-16f);
    float4 b = *(const float4*)(bias + lane * 4);
    float4 o;
    o.x = elu(acc.x * inv + b.x);
    o.y = elu(acc.y * inv + b.y);
    o.z = elu(acc.z * inv + b.z);
    o.w = elu(acc.w * inv + b.w);
    *(float4*)(g_h2 + (size_t)n * 128 + lane * 4) = o;
}

// ---------------- global mean pool ----------------
__global__ void k_pool(const int* __restrict__ batch) {
    int g = blockIdx.x;
    __shared__ int s_lo, s_hi;
    if (threadIdx.x == 0) {
        int lo = 0, hi = NN;
        while (lo < hi) { int mid = (lo + hi) >> 1; if (batch[mid] < g) lo = mid + 1; else hi = mid; }
        s_lo = lo;
        lo = 0; hi = NN;
        while (lo < hi) { int mid = (lo + hi) >> 1; if (batch[mid] < g + 1) lo = mid + 1; else hi = mid; }
        s_hi = lo;
    }
    __syncthreads();
    int lo = s_lo, hi = s_hi;
    int c = threadIdx.x;
    float acc = 0.f;
    for (int n = lo; n < hi; n++) acc += g_h2[(size_t)n * 128 + c];
    float cnt = (float)(hi - lo);
    g_pooled[g * 128 + c] = acc / fmaxf(cnt, 1.f);
}

// ---------------- final MLP ----------------
__global__ void k_mlp(const float* __restrict__ lin1_w, const float* __restrict__ lin1_b,
                      const float* __restrict__ lin2_w, const float* __restrict__ lin2_b,
                      float* __restrict__ out) {
    int g = blockIdx.x;
    int t = threadIdx.x;
    __shared__ float sp[128];
    __shared__ float sz[128];
    sp[t] = g_pooled[g * 128 + t];
    __syncthreads();
    float acc = lin1_b[t];
    #pragma unroll 8
    for (int c = 0; c < 128; c++) acc += sp[c] * lin1_w[c * 128 + t];
    sz[t] = fmaxf(acc, 0.f) * lin2_w[t];
    __syncthreads();
    for (int o = 64; o; o >>= 1) {
        if (t < o) sz[t] += sz[t + o];
        __syncthreads();
    }
    if (t == 0) out[g] = sz[0] + lin2_b[0];
}

// ---------------- launch ----------------
extern "C" void kernel_launch(void* const* d_in, const int* in_sizes, int n_in,
                              void* d_out, int out_size) {
    const float* x      = (const float*)d_in[0];
    const int*   ei     = (const int*)d_in[1];
    const int*   batch  = (const int*)d_in[2];
    const float* W1     = (const float*)d_in[3];
    const float* a_src1 = (const float*)d_in[4];
    const float* a_dst1 = (const float*)d_in[5];
    const float* b1     = (const float*)d_in[6];
    const float* W2     = (const float*)d_in[7];
    const float* a_src2 = (const float*)d_in[8];
    const float* a_dst2 = (const float*)d_in[9];
    const float* b2     = (const float*)d_in[10];
    const float* lin1_w = (const float*)d_in[11];
    const float* lin1_b = (const float*)d_in[12];
    const float* lin2_w = (const float*)d_in[13];
    const float* lin2_b = (const float*)d_in[14];
    float* out = (float*)d_out;

    int E0 = in_sizes[1] / 2;       // 320000
    int E  = E0 + NN;               // 330000

    // CSR build
    k_init_counts<<<(NN + 255) / 256, 256>>>();
    k_count<<<(E + 255) / 256, 256>>>(ei, E0);
    k_scan<<<1, 1024>>>();
    k_scatter<<<(E + 255) / 256, 256>>>(ei, E0);

    // layer 1 (input-space aggregation)
    k_va<<<4, 256>>>(W1, a_src1, a_dst1);
    k_alpha1n<<<(NN + 7) / 8, 256>>>(x);
    k_gather1n<<<NN, 128>>>(x);

    // h1[:, z*128:+128] = elu( agg_z @ W1[:, z*128:+128] + b1_z ), z = 0..7
    {
        dim3 grid(2, (NN + 127) / 128, 8);
        k_mma<<<grid, 256>>>(W1, b1, NN, 128,
                             /*lda=*/1024, /*ldb=*/1024, /*ldc=*/1024,
                             /*a_sel=*/1, /*c_sel=*/1,
                             /*hsA=*/128, /*hsB=*/128LL, /*hsC=*/128LL,
                             /*do_elu=*/1);
    }

    // layer 2 GEMM: xl2 = h1 @ W2, K=1024 split into 4 chunks of 256
    {
        dim3 grid(2, (NN + 127) / 128, KSPLIT);
        k_mma<<<grid, 256>>>(W2, nullptr, NN, 256,
                             /*lda=*/1024, /*ldb=*/128, /*ldc=*/128,
                             /*a_sel=*/2, /*c_sel=*/0,
                             /*hsA=*/256, /*hsB=*/256LL * 128, /*hsC=*/(long long)NN * 128,
                             /*do_elu=*/0);
    }
    k_alpha2<<<(NN * 32 + 255) / 256, 256>>>(a_src2, a_dst2);
    k_gather2<<<(NN * 32 + 255) / 256, 256>>>(b2);

    // pool + MLP head
    k_pool<<<NG, 128>>>(batch);
    k_mlp<<<NG, 128>>>(lin1_w, lin1_b, lin2_w, lin2_b, out);
}

// round 10
// speedup vs baseline: 1.5091x; 1.0762x over previous
#include <cuda_runtime.h>
#include <math.h>

#define NN      10000
#define NG      64
#define ET      330000   // E0 + self loops
#define KSPLIT  4

// ---------------- device scratch (static; no allocation) ----------------
__device__ float g_xl1[NN * 1024];   // layer1 per-head aggregate, tf32-rounded [N, 8*128]
__device__ float g_h1 [NN * 1024];   // layer1 output, tf32-rounded [N, 1024]
__device__ float g_as1[NN * 8];
__device__ float g_ad1[NN * 8];
__device__ float g_vas[128 * 8];
__device__ float g_vad[128 * 8];
__device__ float g_w1r[128 * 1024];  // W1 tf32-rounded
__device__ float g_w2r[1024 * 128];  // W2 tf32-rounded
__device__ float g_xl2p[KSPLIT * NN * 128];  // layer2 GEMM partials (full fp32)
__device__ float g_xl2[NN * 128];
__device__ float g_as2[NN];
__device__ float g_ad2[NN];
__device__ float g_h2 [NN * 128];
__device__ float g_pooled[NG * 128];
__device__ int   g_cnt[NN];
__device__ int   g_cur[NN];
__device__ int   g_off[NN + 1];
__device__ int   g_csr_src[ET];

// ---------------- helpers ----------------
__device__ __forceinline__ void get_edge(const int* ei, int E0, int e,
                                         int& s, int& d) {
    if (e < E0) { s = ei[e]; d = ei[E0 + e]; }
    else        { s = e - E0; d = e - E0; }
}

__device__ __forceinline__ float lrelu(float x) { return x > 0.f ? x : 0.2f * x; }
__device__ __forceinline__ float elu(float x)   { return x > 0.f ? x : expm1f(x); }

__device__ __forceinline__ float tf32r(float x) {
    unsigned u;
    asm("cvt.rna.tf32.f32 %0, %1;" : "=r"(u) : "f"(x));
    return __uint_as_float(u);
}

__device__ __forceinline__ void mma_tf32(float* d, const unsigned* a, const unsigned* b) {
    asm volatile(
        "mma.sync.aligned.m16n8k8.row.col.f32.tf32.tf32.f32 "
        "{%0,%1,%2,%3},{%4,%5,%6,%7},{%8,%9},{%0,%1,%2,%3};"
        : "+f"(d[0]), "+f"(d[1]), "+f"(d[2]), "+f"(d[3])
        : "r"(a[0]), "r"(a[1]), "r"(a[2]), "r"(a[3]), "r"(b[0]), "r"(b[1]));
}

#define CP_ASYNC16(dst_u32, src_ptr) \
    asm volatile("cp.async.cg.shared.global [%0], [%1], 16;" :: "r"(dst_u32), "l"(src_ptr))
#define CP_COMMIT()  asm volatile("cp.async.commit_group;")
#define CP_WAIT1()   asm volatile("cp.async.wait_group 1;")

// ---------------- pre-round weights to tf32 (RNA) ----------------
__global__ void k_round(const float* __restrict__ W1, const float* __restrict__ W2) {
    int i = blockIdx.x * blockDim.x + threadIdx.x;
    if (i < 128 * 1024) g_w1r[i] = tf32r(W1[i]);
    if (i < 1024 * 128) g_w2r[i] = tf32r(W2[i]);
}

// ---------------- CSR build ----------------
__global__ void k_count(const int* ei, int E0) {
    int e = blockIdx.x * blockDim.x + threadIdx.x;
    if (e >= E0 + NN) return;
    int s, d; get_edge(ei, E0, e, s, d);
    if ((unsigned)s >= NN || (unsigned)d >= NN) return;
    atomicAdd(&g_cnt[d], 1);
}

// single-block scan over 10000 counts -> exclusive offsets; resets cnt/cur for next replay
__global__ void k_scan() {
    __shared__ int part[1024];
    const int CH = 10;
    int tid = threadIdx.x;
    int local[CH];
    int s = 0;
    #pragma unroll
    for (int i = 0; i < CH; i++) {
        int idx = tid * CH + i;
        int v = (idx < NN) ? g_cnt[idx] : 0;
        local[i] = s; s += v;
        if (idx < NN) { g_cnt[idx] = 0; g_cur[idx] = 0; }   // reset for next run
    }
    part[tid] = s;
    __syncthreads();
    for (int o = 1; o < 1024; o <<= 1) {
        int v = (tid >= o) ? part[tid - o] : 0;
        __syncthreads();
        part[tid] += v;
        __syncthreads();
    }
    int pre = tid ? part[tid - 1] : 0;
    #pragma unroll
    for (int i = 0; i < CH; i++) {
        int idx = tid * CH + i;
        if (idx < NN) g_off[idx] = pre + local[i];
    }
    if (tid == 1023) g_off[NN] = part[1023];
}

__global__ void k_scatter(const int* ei, int E0) {
    int e = blockIdx.x * blockDim.x + threadIdx.x;
    if (e >= E0 + NN) return;
    int s, d; get_edge(ei, E0, e, s, d);
    if ((unsigned)s >= NN || (unsigned)d >= NN) return;
    int pos = atomicAdd(&g_cur[d], 1);
    g_csr_src[g_off[d] + pos] = s;
}

// ---------------- va = W1 . a  (per head) ----------------
__global__ void k_va(const float* __restrict__ W1, const float* __restrict__ as,
                     const float* __restrict__ ad) {
    int t = blockIdx.x * blockDim.x + threadIdx.x;
    if (t >= 1024) return;
    int k = t >> 3, h = t & 7;
    float ss = 0.f, dd = 0.f;
    const float* wrow = W1 + (size_t)k * 1024 + h * 128;
    const float* asr = as + h * 128;
    const float* adr = ad + h * 128;
    #pragma unroll 8
    for (int c = 0; c < 128; c++) { float w = wrow[c]; ss += w * asr[c]; dd += w * adr[c]; }
    g_vas[k * 8 + h] = ss;
    g_vad[k * 8 + h] = dd;
}

// ---------------- layer1 logits ----------------
__global__ void k_alpha1n(const float* __restrict__ x) {
    int n = blockIdx.x * 8 + (threadIdx.x >> 5);
    if (n >= NN) return;
    int lane = threadIdx.x & 31;
    float4 xv = *(const float4*)(x + (size_t)n * 128 + lane * 4);
    float xa[4] = {xv.x, xv.y, xv.z, xv.w};
    float s[8] = {0,0,0,0,0,0,0,0}, d[8] = {0,0,0,0,0,0,0,0};
    #pragma unroll
    for (int j = 0; j < 4; j++) {
        int k = lane * 4 + j;
        float xj = xa[j];
        float4 v0 = *(const float4*)(g_vas + k * 8);
        float4 v1 = *(const float4*)(g_vas + k * 8 + 4);
        float4 w0 = *(const float4*)(g_vad + k * 8);
        float4 w1 = *(const float4*)(g_vad + k * 8 + 4);
        s[0] += xj * v0.x; s[1] += xj * v0.y; s[2] += xj * v0.z; s[3] += xj * v0.w;
        s[4] += xj * v1.x; s[5] += xj * v1.y; s[6] += xj * v1.z; s[7] += xj * v1.w;
        d[0] += xj * w0.x; d[1] += xj * w0.y; d[2] += xj * w0.z; d[3] += xj * w0.w;
        d[4] += xj * w1.x; d[5] += xj * w1.y; d[6] += xj * w1.z; d[7] += xj * w1.w;
    }
    #pragma unroll
    for (int hh = 0; hh < 8; hh++)
        for (int o = 16; o; o >>= 1) {
            s[hh] += __shfl_xor_sync(0xffffffffu, s[hh], o);
            d[hh] += __shfl_xor_sync(0xffffffffu, d[hh], o);
        }
    if (lane == 0) {
        #pragma unroll
        for (int hh = 0; hh < 8; hh++) {
            g_as1[n * 8 + hh] = s[hh];
            g_ad1[n * 8 + hh] = d[hh];
        }
    }
}

// ---------------- layer1 gather (input space); writes tf32-rounded ----------------
__global__ void k_gather1n(const float* __restrict__ x) {
    __shared__ float s_m[8], s_inv[8], s_ad[8];
    __shared__ float red_m[128], red_s[128];
    __shared__ float ws[32][9];
    __shared__ int   ssrc[32];

    int n = blockIdx.x;
    int t = threadIdx.x;
    int beg = g_off[n], end = g_off[n + 1];

    int h = t & 7, slot = t >> 3;
    float advh = g_ad1[n * 8 + h];
    if (t < 8) s_ad[t] = advh;
    float m = -INFINITY, ssum = 0.f;
    for (int i = beg + slot; i < end; i += 16) {
        int s = g_csr_src[i];
        float e = lrelu(g_as1[s * 8 + h] + advh);
        if (e > m) { ssum = ssum * __expf(m - e) + 1.f; m = e; }
        else        ssum += __expf(e - m);
    }
    red_m[t] = m; red_s[t] = ssum;
    __syncthreads();
    if (t < 8) {
        float M = -INFINITY;
        for (int i = t; i < 128; i += 8) M = fmaxf(M, red_m[i]);
        float S = 0.f;
        for (int i = t; i < 128; i += 8) {
            float mi = red_m[i];
            if (mi > -INFINITY) S += red_s[i] * __expf(mi - M);
        }
        s_m[t] = M;
        s_inv[t] = 1.f / (S + 1e-16f);
    }
    __syncthreads();

    int lane = t & 31, wid = t >> 5;
    float acc[8] = {0,0,0,0,0,0,0,0};
    for (int base = beg; base < end; base += 32) {
        int cnt = min(32, end - base);
        if (wid == 0 && lane < cnt) {
            int s = g_csr_src[base + lane];
            ssrc[lane] = s;
            float4 a0 = *(const float4*)(g_as1 + s * 8);
            float4 a1 = *(const float4*)(g_as1 + s * 8 + 4);
            ws[lane][0] = __expf(lrelu(a0.x + s_ad[0]) - s_m[0]);
            ws[lane][1] = __expf(lrelu(a0.y + s_ad[1]) - s_m[1]);
            ws[lane][2] = __expf(lrelu(a0.z + s_ad[2]) - s_m[2]);
            ws[lane][3] = __expf(lrelu(a0.w + s_ad[3]) - s_m[3]);
            ws[lane][4] = __expf(lrelu(a1.x + s_ad[4]) - s_m[4]);
            ws[lane][5] = __expf(lrelu(a1.y + s_ad[5]) - s_m[5]);
            ws[lane][6] = __expf(lrelu(a1.z + s_ad[6]) - s_m[6]);
            ws[lane][7] = __expf(lrelu(a1.w + s_ad[7]) - s_m[7]);
        }
        __syncthreads();
        #pragma unroll 4
        for (int i = 0; i < cnt; i++) {
            float xv = x[(size_t)ssrc[i] * 128 + t];
            #pragma unroll
            for (int hh = 0; hh < 8; hh++) acc[hh] += ws[i][hh] * xv;
        }
        __syncthreads();
    }

    float* dst = g_xl1 + (size_t)n * 1024 + t;
    #pragma unroll
    for (int hh = 0; hh < 8; hh++) dst[hh * 128] = tf32r(acc[hh] * s_inv[hh]);
}

// ---------------- TF32 tensor-core GEMM, cp.async double-buffered ----------------
// Inputs are pre-rounded to tf32 (producers / k_round); raw bits fed to MMA.
// Block tile 128m x 64n, BK=16, 256 threads (8 warps: 4m x 2n, warp tile 32x32).
// A smem [m][k] stride 20 (conflict-free), B smem [k][n] stride 72 (conflict-free).
// a_sel: 1 -> g_xl1, 2 -> g_h1.  b_sel: 1 -> g_w1r, 2 -> g_w2r.
// c_sel: 0 -> g_xl2p, 1 -> g_h1 (tf32-rounded store).
#define AS_STRIDE 20
#define BS_STRIDE 72
__global__ void k_mma(const float* __restrict__ bias,
                      int M, int KC, int lda, int ldb, int ldc,
                      int a_sel, int b_sel, int c_sel,
                      int hsA, long long hsB, long long hsC, int do_elu) {
    int z = blockIdx.z;
    const float* A = (a_sel == 1 ? (const float*)g_xl1 : (const float*)g_h1) + (long long)z * hsA;
    const float* B = (b_sel == 1 ? (const float*)g_w1r : (const float*)g_w2r) + (long long)z * hsB;
    float* C = (c_sel == 0 ? g_xl2p : g_h1) + (long long)z * hsC;

    __shared__ float As[2][128 * AS_STRIDE];
    __shared__ float Bs[2][16 * BS_STRIDE];

    const int tid  = threadIdx.x;
    const int lane = tid & 31;
    const int wid  = tid >> 5;
    const int tq   = lane >> 2;
    const int t4   = lane & 3;
    const int warp_m = (wid >> 1) * 32;
    const int warp_n = (wid & 1) * 32;

    const int brow = blockIdx.y * 128;
    const int bcol = blockIdx.x * 64;

    const int a_row = tid >> 1;          // 0..127
    const int a_kq  = (tid & 1) * 8;     // 0 or 8
    const int b_k   = tid >> 4;          // 0..15
    const int b_c   = (tid & 15) * 4;    // 0..60

    const int  a_grow  = brow + a_row;
    const bool a_valid = (a_grow < M);
    const float* a_src = A + (size_t)a_grow * lda;

    unsigned asm_base[2], bsm_base[2];
    #pragma unroll
    for (int b = 0; b < 2; b++) {
        asm_base[b] = (unsigned)__cvta_generic_to_shared(&As[b][0]);
        bsm_base[b] = (unsigned)__cvta_generic_to_shared(&Bs[b][0]);
    }

    float acc[2][4][4];
    #pragma unroll
    for (int i = 0; i < 2; i++)
        #pragma unroll
        for (int j = 0; j < 4; j++)
            #pragma unroll
            for (int r = 0; r < 4; r++) acc[i][j][r] = 0.f;

    auto stage = [&](int bf, int k0) {
        #pragma unroll
        for (int half = 0; half < 2; half++) {
            int kk = a_kq + half * 4;
            unsigned dst = asm_base[bf] + (a_row * AS_STRIDE + kk) * 4;
            if (a_valid) { CP_ASYNC16(dst, a_src + k0 + kk); }
            else *(float4*)&As[bf][a_row * AS_STRIDE + kk] = make_float4(0.f, 0.f, 0.f, 0.f);
        }
        unsigned dstb = bsm_base[bf] + (b_k * BS_STRIDE + b_c) * 4;
        CP_ASYNC16(dstb, B + (size_t)(k0 + b_k) * ldb + bcol + b_c);
    };

    stage(0, 0);
    CP_COMMIT();

    int buf = 0;
    for (int k0 = 0; k0 < KC; k0 += 16) {
        if (k0 + 16 < KC) stage(buf ^ 1, k0 + 16);
        CP_COMMIT();                 // uniform group numbering (may be empty)
        CP_WAIT1();                  // current buffer's group complete
        __syncthreads();

        const float* Ab = As[buf];
        const float* Bb = Bs[buf];
        #pragma unroll
        for (int ks = 0; ks < 16; ks += 8) {
            unsigned a[2][4];
            #pragma unroll
            for (int fm = 0; fm < 2; fm++) {
                int r = warp_m + fm * 16 + tq;
                a[fm][0] = __float_as_uint(Ab[ r      * AS_STRIDE + ks + t4    ]);
                a[fm][1] = __float_as_uint(Ab[(r + 8) * AS_STRIDE + ks + t4    ]);
                a[fm][2] = __float_as_uint(Ab[ r      * AS_STRIDE + ks + t4 + 4]);
                a[fm][3] = __float_as_uint(Ab[(r + 8) * AS_STRIDE + ks + t4 + 4]);
            }
            unsigned b[4][2];
            #pragma unroll
            for (int fn = 0; fn < 4; fn++) {
                int c = warp_n + fn * 8 + tq;
                b[fn][0] = __float_as_uint(Bb[(ks + t4    ) * BS_STRIDE + c]);
                b[fn][1] = __float_as_uint(Bb[(ks + t4 + 4) * BS_STRIDE + c]);
            }
            #pragma unroll
            for (int fm = 0; fm < 2; fm++)
                #pragma unroll
                for (int fn = 0; fn < 4; fn++)
                    mma_tf32(acc[fm][fn], a[fm], b[fn]);
        }
        buf ^= 1;
        __syncthreads();             // readers done before restage overwrites
    }

    #pragma unroll
    for (int fm = 0; fm < 2; fm++) {
        int r0 = brow + warp_m + fm * 16 + tq;
        int r1 = r0 + 8;
        #pragma unroll
        for (int fn = 0; fn < 4; fn++) {
            int c = bcol + warp_n + fn * 8 + 2 * t4;
            float2 v0 = make_float2(acc[fm][fn][0], acc[fm][fn][1]);
            float2 v1 = make_float2(acc[fm][fn][2], acc[fm][fn][3]);
            if (do_elu) {
                float2 bv = *(const float2*)(bias + (long long)z * hsC + c);
                // h1 feeds the next tf32 GEMM: round at write (RNA)
                v0.x = tf32r(elu(v0.x + bv.x)); v0.y = tf32r(elu(v0.y + bv.y));
                v1.x = tf32r(elu(v1.x + bv.x)); v1.y = tf32r(elu(v1.y + bv.y));
            }
            if (r0 < M) *(float2*)(C + (size_t)r0 * ldc + c) = v0;
            if (r1 < M) *(float2*)(C + (size_t)r1 * ldc + c) = v1;
        }
    }
}

// ---------------- layer2: reduce k-split partials + logits ----------------
__global__ void k_alpha2(const float* __restrict__ a_src,
                         const float* __restrict__ a_dst) {
    int n = blockIdx.x * (blockDim.x >> 5) + (threadIdx.x >> 5);
    if (n >= NN) return;
    int lane = threadIdx.x & 31;
    size_t idx = (size_t)n * 128 + lane * 4;
    float4 v = *(const float4*)(g_xl2p + idx);
    #pragma unroll
    for (int z = 1; z < KSPLIT; z++) {
        float4 p = *(const float4*)(g_xl2p + (size_t)z * NN * 128 + idx);
        v.x += p.x; v.y += p.y; v.z += p.z; v.w += p.w;
    }
    *(float4*)(g_xl2 + idx) = v;

    const float4 as = *(const float4*)(a_src + lane * 4);
    const float4 ad = *(const float4*)(a_dst + lane * 4);
    float s = v.x * as.x + v.y * as.y + v.z * as.z + v.w * as.w;
    float d = v.x * ad.x + v.y * ad.y + v.z * ad.z + v.w * ad.w;
    for (int o = 16; o; o >>= 1) {
        s += __shfl_xor_sync(0xffffffffu, s, o);
        d += __shfl_xor_sync(0xffffffffu, d, o);
    }
    if (lane == 0) { g_as2[n] = s; g_ad2[n] = d; }
}

// ---------------- layer2 gather ----------------
__global__ void k_gather2(const float* __restrict__ bias) {
    int n = blockIdx.x * (blockDim.x >> 5) + (threadIdx.x >> 5);
    if (n >= NN) return;
    int lane = threadIdx.x & 31;
    int beg = g_off[n], end = g_off[n + 1];
    float adv = g_ad2[n];

    float m = -INFINITY;
    for (int i = beg + lane; i < end; i += 32)
        m = fmaxf(m, lrelu(g_as2[g_csr_src[i]] + adv));
    for (int o = 16; o; o >>= 1) m = fmaxf(m, __shfl_xor_sync(0xffffffffu, m, o));

    float4 acc = make_float4(0.f, 0.f, 0.f, 0.f);
    float denom = 0.f;
    for (int i = beg; i < end; i++) {
        int s = g_csr_src[i];
        float w = __expf(lrelu(g_as2[s] + adv) - m);
        denom += w;
        float4 v = *(const float4*)(g_xl2 + (size_t)s * 128 + lane * 4);
        acc.x += w * v.x; acc.y += w * v.y; acc.z += w * v.z; acc.w += w * v.w;
    }
    float inv = 1.f / (denom + 1e-16f);
    float4 b = *(const float4*)(bias + lane * 4);
    float4 o;
    o.x = elu(acc.x * inv + b.x);
    o.y = elu(acc.y * inv + b.y);
    o.z = elu(acc.z * inv + b.z);
    o.w = elu(acc.w * inv + b.w);
    *(float4*)(g_h2 + (size_t)n * 128 + lane * 4) = o;
}

// ---------------- global mean pool ----------------
__global__ void k_pool(const int* __restrict__ batch) {
    int g = blockIdx.x;
    __shared__ int s_lo, s_hi;
    if (threadIdx.x == 0) {
        int lo = 0, hi = NN;
        while (lo < hi) { int mid = (lo + hi) >> 1; if (batch[mid] < g) lo = mid + 1; else hi = mid; }
        s_lo = lo;
        lo = 0; hi = NN;
        while (lo < hi) { int mid = (lo + hi) >> 1; if (batch[mid] < g + 1) lo = mid + 1; else hi = mid; }
        s_hi = lo;
    }
    __syncthreads();
    int lo = s_lo, hi = s_hi;
    int c = threadIdx.x;
    float acc = 0.f;
    for (int n = lo; n < hi; n++) acc += g_h2[(size_t)n * 128 + c];
    float cnt = (float)(hi - lo);
    g_pooled[g * 128 + c] = acc / fmaxf(cnt, 1.f);
}

// ---------------- final MLP ----------------
__global__ void k_mlp(const float* __restrict__ lin1_w, const float* __restrict__ lin1_b,
                      const float* __restrict__ lin2_w, const float* __restrict__ lin2_b,
                      float* __restrict__ out) {
    int g = blockIdx.x;
    int t = threadIdx.x;
    __shared__ float sp[128];
    __shared__ float sz[128];
    sp[t] = g_pooled[g * 128 + t];
    __syncthreads();
    float acc = lin1_b[t];
    #pragma unroll 8
    for (int c = 0; c < 128; c++) acc += sp[c] * lin1_w[c * 128 + t];
    sz[t] = fmaxf(acc, 0.f) * lin2_w[t];
    __syncthreads();
    for (int o = 64; o; o >>= 1) {
        if (t < o) sz[t] += sz[t + o];
        __syncthreads();
    }
    if (t == 0) out[g] = sz[0] + lin2_b[0];
}

// ---------------- launch ----------------
extern "C" void kernel_launch(void* const* d_in, const int* in_sizes, int n_in,
                              void* d_out, int out_size) {
    const float* x      = (const float*)d_in[0];
    const int*   ei     = (const int*)d_in[1];
    const int*   batch  = (const int*)d_in[2];
    const float* W1     = (const float*)d_in[3];
    const float* a_src1 = (const float*)d_in[4];
    const float* a_dst1 = (const float*)d_in[5];
    const float* b1     = (const float*)d_in[6];
    const float* W2     = (const float*)d_in[7];
    const float* a_src2 = (const float*)d_in[8];
    const float* a_dst2 = (const float*)d_in[9];
    const float* b2     = (const float*)d_in[10];
    const float* lin1_w = (const float*)d_in[11];
    const float* lin1_b = (const float*)d_in[12];
    const float* lin2_w = (const float*)d_in[13];
    const float* lin2_b = (const float*)d_in[14];
    float* out = (float*)d_out;

    int E0 = in_sizes[1] / 2;       // 320000
    int E  = E0 + NN;               // 330000

    // CSR build (g_cnt/g_cur zeroed by previous run's k_scan; zero at load)
    k_count<<<(E + 255) / 256, 256>>>(ei, E0);
    k_round<<<(128 * 1024 + 255) / 256, 256>>>(W1, W2);   // overlaps CSR chain
    k_scan<<<1, 1024>>>();
    k_scatter<<<(E + 255) / 256, 256>>>(ei, E0);

    // layer 1 (input-space aggregation)
    k_va<<<4, 256>>>(W1, a_src1, a_dst1);
    k_alpha1n<<<(NN + 7) / 8, 256>>>(x);
    k_gather1n<<<NN, 128>>>(x);

    // h1[:, z*128:+128] = elu( agg_z @ W1[:, z*128:+128] + b1_z ), z = 0..7
    {
        dim3 grid(2, (NN + 127) / 128, 8);
        k_mma<<<grid, 256>>>(b1, NN, 128,
                             /*lda=*/1024, /*ldb=*/1024, /*ldc=*/1024,
                             /*a_sel=*/1, /*b_sel=*/1, /*c_sel=*/1,
                             /*hsA=*/128, /*hsB=*/128LL, /*hsC=*/128LL,
                             /*do_elu=*/1);
    }

    // layer 2 GEMM: xl2 = h1 @ W2, K=1024 split into 4 chunks of 256
    {
        dim3 grid(2, (NN + 127) / 128, KSPLIT);
        k_mma<<<grid, 256>>>(nullptr, NN, 256,
                             /*lda=*/1024, /*ldb=*/128, /*ldc=*/128,
                             /*a_sel=*/2, /*b_sel=*/2, /*c_sel=*/0,
                             /*hsA=*/256, /*hsB=*/256LL * 128, /*hsC=*/(long long)NN * 128,
                             /*do_elu=*/0);
    }
    k_alpha2<<<(NN * 32 + 255) / 256, 256>>>(a_src2, a_dst2);
    k_gather2<<<(NN * 32 + 255) / 256, 256>>>(b2);

    // pool + MLP head
    k_pool<<<NG, 128>>>(batch);
    k_mlp<<<NG, 128>>>(lin1_w, lin1_b, lin2_w, lin2_b, out);
}

// round 13
// speedup vs baseline: 1.5489x; 1.0264x over previous
#include <cuda_runtime.h>
#include <math.h>

#define NN      10000
#define NG      64
#define ET      330000   // E0 + self loops
#define KSPLIT  4

// ---------------- device scratch (static; no allocation) ----------------
__device__ float g_xl1[NN * 1024];   // layer1 per-head aggregate, tf32-rounded [N, 8*128]
__device__ float g_h1 [NN * 1024];   // layer1 output, tf32-rounded [N, 1024]
__device__ float g_as1[NN * 8];
__device__ float g_ad1[NN * 8];
__device__ float g_vas[128 * 8];
__device__ float g_vad[128 * 8];
__device__ float g_w1r[128 * 1024];  // W1 tf32-rounded
__device__ float g_w2r[1024 * 128];  // W2 tf32-rounded
__device__ float g_xl2p[KSPLIT * NN * 128];  // layer2 GEMM partials (full fp32)
__device__ float g_xl2[NN * 128];
__device__ float g_as2[NN];
__device__ float g_ad2[NN];
__device__ float g_h2 [NN * 128];
__device__ int   g_cnt[NN];
__device__ int   g_cur[NN];
__device__ int   g_off[NN + 1];
__device__ int   g_csr_src[ET];

// ---------------- helpers ----------------
__device__ __forceinline__ void get_edge(const int* ei, int E0, int e,
                                         int& s, int& d) {
    if (e < E0) { s = ei[e]; d = ei[E0 + e]; }
    else        { s = e - E0; d = e - E0; }
}

__device__ __forceinline__ float lrelu(float x) { return x > 0.f ? x : 0.2f * x; }
__device__ __forceinline__ float elu(float x)   { return x > 0.f ? x : expm1f(x); }

__device__ __forceinline__ float tf32r(float x) {
    unsigned u;
    asm("cvt.rna.tf32.f32 %0, %1;" : "=r"(u) : "f"(x));
    return __uint_as_float(u);
}

__device__ __forceinline__ void mma_tf32(float* d, const unsigned* a, const unsigned* b) {
    asm volatile(
        "mma.sync.aligned.m16n8k8.row.col.f32.tf32.tf32.f32 "
        "{%0,%1,%2,%3},{%4,%5,%6,%7},{%8,%9},{%0,%1,%2,%3};"
        : "+f"(d[0]), "+f"(d[1]), "+f"(d[2]), "+f"(d[3])
        : "r"(a[0]), "r"(a[1]), "r"(a[2]), "r"(a[3]), "r"(b[0]), "r"(b[1]));
}

#define CP_ASYNC16(dst_u32, src_ptr) \
    asm volatile("cp.async.cg.shared.global [%0], [%1], 16;" :: "r"(dst_u32), "l"(src_ptr))
#define CP_COMMIT()  asm volatile("cp.async.commit_group;")
#define CP_WAIT1()   asm volatile("cp.async.wait_group 1;")

// ---------------- fused prologue: count || round weights || va ----------------
// blocks [0, NB_CNT)            : edge degree count
// blocks [NB_CNT, +NB_RND)      : tf32-round W1/W2
// blocks [NB_CNT+NB_RND, +4)    : va = W1 . a per head
#define NB_CNT 1290      // ceil(330000/256)
#define NB_RND 512       // ceil(131072/256)
__global__ void k_pro(const int* __restrict__ ei, int E0,
                      const float* __restrict__ W1, const float* __restrict__ W2,
                      const float* __restrict__ as, const float* __restrict__ ad) {
    int bid = blockIdx.x;
    if (bid < NB_CNT) {
        int e = bid * 256 + threadIdx.x;
        if (e >= E0 + NN) return;
        int s, d; get_edge(ei, E0, e, s, d);
        if ((unsigned)s >= NN || (unsigned)d >= NN) return;
        atomicAdd(&g_cnt[d], 1);
    } else if (bid < NB_CNT + NB_RND) {
        int i = (bid - NB_CNT) * 256 + threadIdx.x;
        if (i < 128 * 1024) { g_w1r[i] = tf32r(W1[i]); g_w2r[i] = tf32r(W2[i]); }
    } else {
        int t = (bid - NB_CNT - NB_RND) * 256 + threadIdx.x;
        if (t >= 1024) return;
        int k = t >> 3, h = t & 7;
        float ss = 0.f, dd = 0.f;
        const float* wrow = W1 + (size_t)k * 1024 + h * 128;
        const float* asr = as + h * 128;
        const float* adr = ad + h * 128;
        #pragma unroll 8
        for (int c = 0; c < 128; c++) { float w = wrow[c]; ss += w * asr[c]; dd += w * adr[c]; }
        g_vas[k * 8 + h] = ss;
        g_vad[k * 8 + h] = dd;
    }
}

// ---------------- scan: counts -> exclusive offsets; resets cnt/cur ----------------
__global__ void k_scan() {
    __shared__ int part[1024];
    const int CH = 10;
    int tid = threadIdx.x;
    int local[CH];
    int s = 0;
    #pragma unroll
    for (int i = 0; i < CH; i++) {
        int idx = tid * CH + i;
        int v = (idx < NN) ? g_cnt[idx] : 0;
        local[i] = s; s += v;
        if (idx < NN) { g_cnt[idx] = 0; g_cur[idx] = 0; }   // reset for next replay
    }
    part[tid] = s;
    __syncthreads();
    for (int o = 1; o < 1024; o <<= 1) {
        int v = (tid >= o) ? part[tid - o] : 0;
        __syncthreads();
        part[tid] += v;
        __syncthreads();
    }
    int pre = tid ? part[tid - 1] : 0;
    #pragma unroll
    for (int i = 0; i < CH; i++) {
        int idx = tid * CH + i;
        if (idx < NN) g_off[idx] = pre + local[i];
    }
    if (tid == 1023) g_off[NN] = part[1023];
}

// ---------------- fused: scatter || layer1 logits ----------------
// blocks [0, NB_CNT): CSR scatter.  blocks [NB_CNT, +1250): alpha1n (8 nodes/block).
__global__ void k_scat_alpha(const int* __restrict__ ei, int E0,
                             const float* __restrict__ x) {
    int bid = blockIdx.x;
    if (bid < NB_CNT) {
        int e = bid * 256 + threadIdx.x;
        if (e >= E0 + NN) return;
        int s, d; get_edge(ei, E0, e, s, d);
        if ((unsigned)s >= NN || (unsigned)d >= NN) return;
        int pos = atomicAdd(&g_cur[d], 1);
        g_csr_src[g_off[d] + pos] = s;
        return;
    }
    int n = (bid - NB_CNT) * 8 + (threadIdx.x >> 5);
    if (n >= NN) return;
    int lane = threadIdx.x & 31;
    float4 xv = *(const float4*)(x + (size_t)n * 128 + lane * 4);
    float xa[4] = {xv.x, xv.y, xv.z, xv.w};
    float s[8] = {0,0,0,0,0,0,0,0}, d[8] = {0,0,0,0,0,0,0,0};
    #pragma unroll
    for (int j = 0; j < 4; j++) {
        int k = lane * 4 + j;
        float xj = xa[j];
        float4 v0 = *(const float4*)(g_vas + k * 8);
        float4 v1 = *(const float4*)(g_vas + k * 8 + 4);
        float4 w0 = *(const float4*)(g_vad + k * 8);
        float4 w1 = *(const float4*)(g_vad + k * 8 + 4);
        s[0] += xj * v0.x; s[1] += xj * v0.y; s[2] += xj * v0.z; s[3] += xj * v0.w;
        s[4] += xj * v1.x; s[5] += xj * v1.y; s[6] += xj * v1.z; s[7] += xj * v1.w;
        d[0] += xj * w0.x; d[1] += xj * w0.y; d[2] += xj * w0.z; d[3] += xj * w0.w;
        d[4] += xj * w1.x; d[5] += xj * w1.y; d[6] += xj * w1.z; d[7] += xj * w1.w;
    }
    #pragma unroll
    for (int hh = 0; hh < 8; hh++)
        for (int o = 16; o; o >>= 1) {
            s[hh] += __shfl_xor_sync(0xffffffffu, s[hh], o);
            d[hh] += __shfl_xor_sync(0xffffffffu, d[hh], o);
        }
    if (lane == 0) {
        #pragma unroll
        for (int hh = 0; hh < 8; hh++) {
            g_as1[n * 8 + hh] = s[hh];
            g_ad1[n * 8 + hh] = d[hh];
        }
    }
}

// ---------------- layer1 gather (input space); writes tf32-rounded ----------------
__global__ void k_gather1n(const float* __restrict__ x) {
    __shared__ float s_m[8], s_inv[8], s_ad[8];
    __shared__ float red_m[128], red_s[128];
    __shared__ float ws[32][9];
    __shared__ int   ssrc[32];

    int n = blockIdx.x;
    int t = threadIdx.x;
    int beg = g_off[n], end = g_off[n + 1];

    int h = t & 7, slot = t >> 3;
    float advh = g_ad1[n * 8 + h];
    if (t < 8) s_ad[t] = advh;
    float m = -INFINITY, ssum = 0.f;
    for (int i = beg + slot; i < end; i += 16) {
        int s = g_csr_src[i];
        float e = lrelu(g_as1[s * 8 + h] + advh);
        if (e > m) { ssum = ssum * __expf(m - e) + 1.f; m = e; }
        else        ssum += __expf(e - m);
    }
    red_m[t] = m; red_s[t] = ssum;
    __syncthreads();
    if (t < 8) {
        float M = -INFINITY;
        for (int i = t; i < 128; i += 8) M = fmaxf(M, red_m[i]);
        float S = 0.f;
        for (int i = t; i < 128; i += 8) {
            float mi = red_m[i];
            if (mi > -INFINITY) S += red_s[i] * __expf(mi - M);
        }
        s_m[t] = M;
        s_inv[t] = 1.f / (S + 1e-16f);
    }
    __syncthreads();

    int lane = t & 31, wid = t >> 5;
    float acc[8] = {0,0,0,0,0,0,0,0};
    for (int base = beg; base < end; base += 32) {
        int cnt = min(32, end - base);
        if (wid == 0 && lane < cnt) {
            int s = g_csr_src[base + lane];
            ssrc[lane] = s;
            float4 a0 = *(const float4*)(g_as1 + s * 8);
            float4 a1 = *(const float4*)(g_as1 + s * 8 + 4);
            ws[lane][0] = __expf(lrelu(a0.x + s_ad[0]) - s_m[0]);
            ws[lane][1] = __expf(lrelu(a0.y + s_ad[1]) - s_m[1]);
            ws[lane][2] = __expf(lrelu(a0.z + s_ad[2]) - s_m[2]);
            ws[lane][3] = __expf(lrelu(a0.w + s_ad[3]) - s_m[3]);
            ws[lane][4] = __expf(lrelu(a1.x + s_ad[4]) - s_m[4]);
            ws[lane][5] = __expf(lrelu(a1.y + s_ad[5]) - s_m[5]);
            ws[lane][6] = __expf(lrelu(a1.z + s_ad[6]) - s_m[6]);
            ws[lane][7] = __expf(lrelu(a1.w + s_ad[7]) - s_m[7]);
        }
        __syncthreads();
        #pragma unroll 4
        for (int i = 0; i < cnt; i++) {
            float xv = x[(size_t)ssrc[i] * 128 + t];
            #pragma unroll
            for (int hh = 0; hh < 8; hh++) acc[hh] += ws[i][hh] * xv;
        }
        __syncthreads();
    }

    float* dst = g_xl1 + (size_t)n * 1024 + t;
    #pragma unroll
    for (int hh = 0; hh < 8; hh++) dst[hh * 128] = tf32r(acc[hh] * s_inv[hh]);
}

// ---------------- TF32 tensor-core GEMM, cp.async double-buffered ----------------
#define AS_STRIDE 20
#define BS_STRIDE 72
__global__ void k_mma(const float* __restrict__ bias,
                      int M, int KC, int lda, int ldb, int ldc,
                      int a_sel, int b_sel, int c_sel,
                      int hsA, long long hsB, long long hsC, int do_elu) {
    int z = blockIdx.z;
    const float* A = (a_sel == 1 ? (const float*)g_xl1 : (const float*)g_h1) + (long long)z * hsA;
    const float* B = (b_sel == 1 ? (const float*)g_w1r : (const float*)g_w2r) + (long long)z * hsB;
    float* C = (c_sel == 0 ? g_xl2p : g_h1) + (long long)z * hsC;

    __shared__ float As[2][128 * AS_STRIDE];
    __shared__ float Bs[2][16 * BS_STRIDE];

    const int tid  = threadIdx.x;
    const int lane = tid & 31;
    const int wid  = tid >> 5;
    const int tq   = lane >> 2;
    const int t4   = lane & 3;
    const int warp_m = (wid >> 1) * 32;
    const int warp_n = (wid & 1) * 32;

    const int brow = blockIdx.y * 128;
    const int bcol = blockIdx.x * 64;

    const int a_row = tid >> 1;
    const int a_kq  = (tid & 1) * 8;
    const int b_k   = tid >> 4;
    const int b_c   = (tid & 15) * 4;

    const int  a_grow  = brow + a_row;
    const bool a_valid = (a_grow < M);
    const float* a_src = A + (size_t)a_grow * lda;

    unsigned asm_base[2], bsm_base[2];
    #pragma unroll
    for (int b = 0; b < 2; b++) {
        asm_base[b] = (unsigned)__cvta_generic_to_shared(&As[b][0]);
        bsm_base[b] = (unsigned)__cvta_generic_to_shared(&Bs[b][0]);
    }

    float acc[2][4][4];
    #pragma unroll
    for (int i = 0; i < 2; i++)
        #pragma unroll
        for (int j = 0; j < 4; j++)
            #pragma unroll
            for (int r = 0; r < 4; r++) acc[i][j][r] = 0.f;

    auto stage = [&](int bf, int k0) {
        #pragma unroll
        for (int half = 0; half < 2; half++) {
            int kk = a_kq + half * 4;
            unsigned dst = asm_base[bf] + (a_row * AS_STRIDE + kk) * 4;
            if (a_valid) { CP_ASYNC16(dst, a_src + k0 + kk); }
            else *(float4*)&As[bf][a_row * AS_STRIDE + kk] = make_float4(0.f, 0.f, 0.f, 0.f);
        }
        unsigned dstb = bsm_base[bf] + (b_k * BS_STRIDE + b_c) * 4;
        CP_ASYNC16(dstb, B + (size_t)(k0 + b_k) * ldb + bcol + b_c);
    };

    stage(0, 0);
    CP_COMMIT();

    int buf = 0;
    for (int k0 = 0; k0 < KC; k0 += 16) {
        if (k0 + 16 < KC) stage(buf ^ 1, k0 + 16);
        CP_COMMIT();
        CP_WAIT1();
        __syncthreads();

        const float* Ab = As[buf];
        const float* Bb = Bs[buf];
        #pragma unroll
        for (int ks = 0; ks < 16; ks += 8) {
            unsigned a[2][4];
            #pragma unroll
            for (int fm = 0; fm < 2; fm++) {
                int r = warp_m + fm * 16 + tq;
                a[fm][0] = __float_as_uint(Ab[ r      * AS_STRIDE + ks + t4    ]);
                a[fm][1] = __float_as_uint(Ab[(r + 8) * AS_STRIDE + ks + t4    ]);
                a[fm][2] = __float_as_uint(Ab[ r      * AS_STRIDE + ks + t4 + 4]);
                a[fm][3] = __float_as_uint(Ab[(r + 8) * AS_STRIDE + ks + t4 + 4]);
            }
            unsigned b[4][2];
            #pragma unroll
            for (int fn = 0; fn < 4; fn++) {
                int c = warp_n + fn * 8 + tq;
                b[fn][0] = __float_as_uint(Bb[(ks + t4    ) * BS_STRIDE + c]);
                b[fn][1] = __float_as_uint(Bb[(ks + t4 + 4) * BS_STRIDE + c]);
            }
            #pragma unroll
            for (int fm = 0; fm < 2; fm++)
                #pragma unroll
                for (int fn = 0; fn < 4; fn++)
                    mma_tf32(acc[fm][fn], a[fm], b[fn]);
        }
        buf ^= 1;
        __syncthreads();
    }

    #pragma unroll
    for (int fm = 0; fm < 2; fm++) {
        int r0 = brow + warp_m + fm * 16 + tq;
        int r1 = r0 + 8;
        #pragma unroll
        for (int fn = 0; fn < 4; fn++) {
            int c = bcol + warp_n + fn * 8 + 2 * t4;
            float2 v0 = make_float2(acc[fm][fn][0], acc[fm][fn][1]);
            float2 v1 = make_float2(acc[fm][fn][2], acc[fm][fn][3]);
            if (do_elu) {
                float2 bv = *(const float2*)(bias + (long long)z * hsC + c);
                v0.x = tf32r(elu(v0.x + bv.x)); v0.y = tf32r(elu(v0.y + bv.y));
                v1.x = tf32r(elu(v1.x + bv.x)); v1.y = tf32r(elu(v1.y + bv.y));
            }
            if (r0 < M) *(float2*)(C + (size_t)r0 * ldc + c) = v0;
            if (r1 < M) *(float2*)(C + (size_t)r1 * ldc + c) = v1;
        }
    }
}

// ---------------- layer2: reduce k-split partials + logits ----------------
__global__ void k_alpha2(const float* __restrict__ a_src,
                         const float* __restrict__ a_dst) {
    int n = blockIdx.x * (blockDim.x >> 5) + (threadIdx.x >> 5);
    if (n >= NN) return;
    int lane = threadIdx.x & 31;
    size_t idx = (size_t)n * 128 + lane * 4;
    float4 v = *(const float4*)(g_xl2p + idx);
    #pragma unroll
    for (int z = 1; z < KSPLIT; z++) {
        float4 p = *(const float4*)(g_xl2p + (size_t)z * NN * 128 + idx);
        v.x += p.x; v.y += p.y; v.z += p.z; v.w += p.w;
    }
    *(float4*)(g_xl2 + idx) = v;

    const float4 as = *(const float4*)(a_src + lane * 4);
    const float4 ad = *(const float4*)(a_dst + lane * 4);
    float s = v.x * as.x + v.y * as.y + v.z * as.z + v.w * as.w;
    float d = v.x * ad.x + v.y * ad.y + v.z * ad.z + v.w * ad.w;
    for (int o = 16; o; o >>= 1) {
        s += __shfl_xor_sync(0xffffffffu, s, o);
        d += __shfl_xor_sync(0xffffffffu, d, o);
    }
    if (lane == 0) { g_as2[n] = s; g_ad2[n] = d; }
}

// ---------------- layer2 gather ----------------
__global__ void k_gather2(const float* __restrict__ bias) {
    int n = blockIdx.x * (blockDim.x >> 5) + (threadIdx.x >> 5);
    if (n >= NN) return;
    int lane = threadIdx.x & 31;
    int beg = g_off[n], end = g_off[n + 1];
    float adv = g_ad2[n];

    float m = -INFINITY;
    for (int i = beg + lane; i < end; i += 32)
        m = fmaxf(m, lrelu(g_as2[g_csr_src[i]] + adv));
    for (int o = 16; o; o >>= 1) m = fmaxf(m, __shfl_xor_sync(0xffffffffu, m, o));

    float4 acc = make_float4(0.f, 0.f, 0.f, 0.f);
    float denom = 0.f;
    for (int i = beg; i < end; i++) {
        int s = g_csr_src[i];
        float w = __expf(lrelu(g_as2[s] + adv) - m);
        denom += w;
        float4 v = *(const float4*)(g_xl2 + (size_t)s * 128 + lane * 4);
        acc.x += w * v.x; acc.y += w * v.y; acc.z += w * v.z; acc.w += w * v.w;
    }
    float inv = 1.f / (denom + 1e-16f);
    float4 b = *(const float4*)(bias + lane * 4);
    float4 o;
    o.x = elu(acc.x * inv + b.x);
    o.y = elu(acc.y * inv + b.y);
    o.z = elu(acc.z * inv + b.z);
    o.w = elu(acc.w * inv + b.w);
    *(float4*)(g_h2 + (size_t)n * 128 + lane * 4) = o;
}

// ---------------- fused global mean pool + MLP head ----------------
__global__ void k_poolmlp(const int* __restrict__ batch,
                          const float* __restrict__ lin1_w, const float* __restrict__ lin1_b,
                          const float* __restrict__ lin2_w, const float* __restrict__ lin2_b,
                          float* __restrict__ out) {
    int g = blockIdx.x;            // 64 blocks, 128 threads
    int t = threadIdx.x;
    __shared__ int s_lo, s_hi;
    __shared__ float sp[128];
    __shared__ float sz[128];
    if (t == 0) {
        int lo = 0, hi = NN;
        while (lo < hi) { int mid = (lo + hi) >> 1; if (batch[mid] < g) lo = mid + 1; else hi = mid; }
        s_lo = lo;
        lo = 0; hi = NN;
        while (lo < hi) { int mid = (lo + hi) >> 1; if (batch[mid] < g + 1) lo = mid + 1; else hi = mid; }
        s_hi = lo;
    }
    __syncthreads();
    int lo = s_lo, hi = s_hi;
    float acc = 0.f;
    for (int n = lo; n < hi; n++) acc += g_h2[(size_t)n * 128 + t];
    sp[t] = acc / fmaxf((float)(hi - lo), 1.f);
    __syncthreads();
    float z = lin1_b[t];
    #pragma unroll 8
    for (int c = 0; c < 128; c++) z += sp[c] * lin1_w[c * 128 + t];
    sz[t] = fmaxf(z, 0.f) * lin2_w[t];
    __syncthreads();
    for (int o = 64; o; o >>= 1) {
        if (t < o) sz[t] += sz[t + o];
        __syncthreads();
    }
    if (t == 0) out[g] = sz[0] + lin2_b[0];
}

// ---------------- launch ----------------
extern "C" void kernel_launch(void* const* d_in, const int* in_sizes, int n_in,
                              void* d_out, int out_size) {
    const float* x      = (const float*)d_in[0];
    const int*   ei     = (const int*)d_in[1];
    const int*   batch  = (const int*)d_in[2];
    const float* W1     = (const float*)d_in[3];
    const float* a_src1 = (const float*)d_in[4];
    const float* a_dst1 = (const float*)d_in[5];
    const float* b1     = (const float*)d_in[6];
    const float* W2     = (const float*)d_in[7];
    const float* a_src2 = (const float*)d_in[8];
    const float* a_dst2 = (const float*)d_in[9];
    const float* b2     = (const float*)d_in[10];
    const float* lin1_w = (const float*)d_in[11];
    const float* lin1_b = (const float*)d_in[12];
    const float* lin2_w = (const float*)d_in[13];
    const float* lin2_b = (const float*)d_in[14];
    float* out = (float*)d_out;

    int E0 = in_sizes[1] / 2;       // 320000

    // 1) count || round || va
    k_pro<<<NB_CNT + NB_RND + 4, 256>>>(ei, E0, W1, W2, a_src1, a_dst1);
    // 2) scan
    k_scan<<<1, 1024>>>();
    // 3) scatter || layer1 logits
    k_scat_alpha<<<NB_CNT + 1250, 256>>>(ei, E0, x);
    // 4) layer1 gather
    k_gather1n<<<NN, 128>>>(x);
    // 5) layer1 head-GEMM (z = head)
    {
        dim3 grid(2, (NN + 127) / 128, 8);
        k_mma<<<grid, 256>>>(b1, NN, 128, 1024, 1024, 1024,
                             1, 1, 1, 128, 128LL, 128LL, 1);
    }
    // 6) layer2 GEMM, K split x4
    {
        dim3 grid(2, (NN + 127) / 128, KSPLIT);
        k_mma<<<grid, 256>>>(nullptr, NN, 256, 1024, 128, 128,
                             2, 2, 0, 256, 256LL * 128, (long long)NN * 128, 0);
    }
    // 7) partial-reduce + layer2 logits
    k_alpha2<<<(NN * 32 + 255) / 256, 256>>>(a_src2, a_dst2);
    // 8) layer2 gather
    k_gather2<<<(NN * 32 + 255) / 256, 256>>>(b2);
    // 9) pool + MLP
    k_poolmlp<<<NG, 128>>>(batch, lin1_w, lin1_b, lin2_w, lin2_b, out);
}